// round 12
// baseline (speedup 1.0000x reference)
#include <cuda_runtime.h>
#include <cuda_bf16.h>
#include <math.h>

#define BATCH 2
#define SEQ   2048
#define DMODEL 1024
#define NHEADS 16
#define DHEAD  64
#define MROWS (BATCH*SEQ)                    // 4096
#define ATT_OFF ((size_t)BATCH*SEQ*DMODEL)
#define NKT 16
#define SPLITK 2
#define PVSTG 3
#define OPSTG 3
#define QKSTG 4

#define PS   ((size_t)MROWS * DMODEL)        // 4M floats
#define PKA  ((size_t)MROWS * 512)           // 2M u32 kpairs
#define PKW  ((size_t)DMODEL * 512)          // 0.5M u32
#define PARTIAL_SZ ((size_t)BATCH * NHEADS * SEQ * NKT)

// gv, go, pctx(2), partial, ipk (q,k,v hi/lo = 6*PKA), wpk (6*PKW), opk (4*PKA)
__device__ float g_scratch[4ull * PS + PARTIAL_SZ + 10ull * PKA + 6ull * PKW];

// scores smem: Qh/Ql/Kh/Kl [128][36] u32 + sums[2][128]
#define SC_SMEM (4 * 128 * 36 * 4 + 256 * 4)
// pv smem
#define PV_PS   (PVSTG * 128 * 20)
#define PV_VS   (PVSTG * 16 * 72)
#define PV_SMEM ((PV_PS + PV_VS + 128) * 4)
// oproj smem
#define OP_AS   (OPSTG * 128 * 20)
#define OP_SMEM (3 * OP_AS * 4)
// proj smem: 4 arrays x QKSTG stages x [128][12]
#define QK_ARR  (QKSTG * 128 * 12)
#define QK_SMEM (4 * QK_ARR * 4)

// ---------------------------------------------------------------------------
__device__ __forceinline__ void mma8(float* d, const unsigned* a, const unsigned* b) {
    asm volatile(
        "mma.sync.aligned.m16n8k8.row.col.f32.tf32.tf32.f32 "
        "{%0,%1,%2,%3}, {%4,%5,%6,%7}, {%8,%9}, {%0,%1,%2,%3};"
        : "+f"(d[0]), "+f"(d[1]), "+f"(d[2]), "+f"(d[3])
        : "r"(a[0]), "r"(a[1]), "r"(a[2]), "r"(a[3]), "r"(b[0]), "r"(b[1]));
}
__device__ __forceinline__ void mma16(float* d, const unsigned* a, const unsigned* b) {
    asm volatile(
        "mma.sync.aligned.m16n8k16.row.col.f32.bf16.bf16.f32 "
        "{%0,%1,%2,%3}, {%4,%5,%6,%7}, {%8,%9}, {%0,%1,%2,%3};"
        : "+f"(d[0]), "+f"(d[1]), "+f"(d[2]), "+f"(d[3])
        : "r"(a[0]), "r"(a[1]), "r"(a[2]), "r"(a[3]), "r"(b[0]), "r"(b[1]));
}
__device__ __forceinline__ void splitbf2(float x, float y, unsigned& hi, unsigned& lo) {
    __nv_bfloat16 hx = __float2bfloat16_rn(x);
    __nv_bfloat16 hy = __float2bfloat16_rn(y);
    __nv_bfloat16 lx = __float2bfloat16_rn(x - __bfloat162float(hx));
    __nv_bfloat16 ly = __float2bfloat16_rn(y - __bfloat162float(hy));
    hi = (unsigned)__bfloat16_as_ushort(hx) | ((unsigned)__bfloat16_as_ushort(hy) << 16);
    lo = (unsigned)__bfloat16_as_ushort(lx) | ((unsigned)__bfloat16_as_ushort(ly) << 16);
}
__device__ __forceinline__ void cpasync16(void* sm, const void* gm) {
    unsigned a = (unsigned)__cvta_generic_to_shared(sm);
    asm volatile("cp.async.cg.shared.global [%0], [%1], 16;" :: "r"(a), "l"(gm));
}

// ---------------------------------------------------------------------------
// Merged prepack: y in [0,6): q,k,v (PKA pairs) then wq,wk,wv (PKW pairs).
// ---------------------------------------------------------------------------
__global__ void prepack_all(const float* __restrict__ q, const float* __restrict__ k,
                            const float* __restrict__ v, const float* __restrict__ wq,
                            const float* __restrict__ wk, const float* __restrict__ wv,
                            unsigned* __restrict__ ipk, unsigned* __restrict__ wpk) {
    const int z = blockIdx.y;
    const int i = blockIdx.x * 256 + threadIdx.x;
    const float* src;
    unsigned *hi, *lo;
    int half;
    if (z < 3) {
        src = (z == 0) ? q : (z == 1) ? k : v;
        hi = ipk + (size_t)z * 2 * PKA; lo = hi + PKA;
        half = (int)(PKA / 2);
    } else {
        int w = z - 3;
        src = (w == 0) ? wq : (w == 1) ? wk : wv;
        hi = wpk + (size_t)w * 2 * PKW; lo = hi + PKW;
        half = (int)(PKW / 2);
    }
    if (i < half) {
        float4 x = ((const float4*)src)[i];
        unsigned h0, l0, h1, l1;
        splitbf2(x.x, x.y, h0, l0);
        splitbf2(x.z, x.w, h1, l1);
        ((uint2*)hi)[i] = make_uint2(h0, h1);
        ((uint2*)lo)[i] = make_uint2(l0, l1);
    }
}

// ---------------------------------------------------------------------------
// q/k/v projections from PREPACKED operands, 3xBF16, cp.async 4-stage.
// z=0: q (packed out), z=1: k (packed out), z=2: v (fp32 out to gv).
// ---------------------------------------------------------------------------
__global__ __launch_bounds__(256, 2)
void gemm_proj_pk(const unsigned* __restrict__ apk, const unsigned* __restrict__ wpk,
                  const float* __restrict__ bq, const float* __restrict__ bk,
                  const float* __restrict__ bv, unsigned* __restrict__ outpk,
                  float* __restrict__ gv) {
    extern __shared__ unsigned qsm[];
    unsigned* Ah = qsm;                 // [QKSTG][128][12]
    unsigned* Al = qsm + QK_ARR;
    unsigned* Wh = qsm + 2 * QK_ARR;
    unsigned* Wl = qsm + 3 * QK_ARR;
    const int z = blockIdx.z;
    const unsigned* Ahi = apk + (size_t)z * 2 * PKA;
    const unsigned* Alo = Ahi + PKA;
    const unsigned* Whi = wpk + (size_t)z * 2 * PKW;
    const unsigned* Wlo = Whi + PKW;
    const float* bias = (z == 0) ? bq : (z == 1) ? bk : bv;

    const int tid = threadIdx.x, lane = tid & 31, warp = tid >> 5;
    const int wm = (warp & 3) * 32, wn = (warp >> 2) * 64, kq = lane & 3;
    const int row0 = blockIdx.y * 128, col0 = blockIdx.x * 128;
    const int ntiles = 512 / 8;

    const int pr = tid >> 1, pk4 = (tid & 1) * 4;
    auto prefetch = [&](int t) {
        int s = t & (QKSTG - 1);
        int kp0 = t * 8;
        cpasync16(&Ah[s*1536 + pr*12 + pk4], &Ahi[(size_t)(row0+pr)*512 + kp0 + pk4]);
        cpasync16(&Al[s*1536 + pr*12 + pk4], &Alo[(size_t)(row0+pr)*512 + kp0 + pk4]);
        cpasync16(&Wh[s*1536 + pr*12 + pk4], &Whi[(size_t)(col0+pr)*512 + kp0 + pk4]);
        cpasync16(&Wl[s*1536 + pr*12 + pk4], &Wlo[(size_t)(col0+pr)*512 + kp0 + pk4]);
        asm volatile("cp.async.commit_group;");
    };
    #pragma unroll
    for (int t = 0; t < QKSTG - 1; t++) prefetch(t);

    float acc[2][8][4] = {};
    for (int t = 0; t < ntiles; t++) {
        int s = t & (QKSTG - 1);
        asm volatile("cp.async.wait_group %0;" :: "n"(QKSTG - 2));
        __syncthreads();
        const unsigned* Ahp = &Ah[s*1536];
        const unsigned* Alp = &Al[s*1536];
        const unsigned* Whp = &Wh[s*1536];
        const unsigned* Wlp = &Wl[s*1536];
        unsigned ah[2][4], al[2][4];
        #pragma unroll
        for (int i = 0; i < 2; i++) {
            int m0 = wm + i * 16 + (lane >> 2);
            ah[i][0] = Ahp[m0*12 + kq];     ah[i][1] = Ahp[(m0+8)*12 + kq];
            ah[i][2] = Ahp[m0*12 + kq+4];   ah[i][3] = Ahp[(m0+8)*12 + kq+4];
            al[i][0] = Alp[m0*12 + kq];     al[i][1] = Alp[(m0+8)*12 + kq];
            al[i][2] = Alp[m0*12 + kq+4];   al[i][3] = Alp[(m0+8)*12 + kq+4];
        }
        #pragma unroll
        for (int j = 0; j < 8; j++) {
            int nb = wn + j * 8 + (lane >> 2);
            unsigned bh2[2] = {Whp[nb*12 + kq], Whp[nb*12 + kq+4]};
            unsigned bl2[2] = {Wlp[nb*12 + kq], Wlp[nb*12 + kq+4]};
            #pragma unroll
            for (int i = 0; i < 2; i++) {
                mma16(acc[i][j], al[i], bh2);
                mma16(acc[i][j], ah[i], bl2);
                mma16(acc[i][j], ah[i], bh2);
            }
        }
        __syncthreads();
        if (t + QKSTG - 1 < ntiles) prefetch(t + QKSTG - 1);
        else asm volatile("cp.async.commit_group;");
    }
    if (z < 2) {
        unsigned* Ohi = outpk + (size_t)z * 2 * PKA;
        unsigned* Olo = Ohi + PKA;
        #pragma unroll
        for (int j = 0; j < 8; j++) {
            int c = col0 + wn + j * 8 + (lane & 3) * 2;
            float2 bb = *(const float2*)&bias[c];
            #pragma unroll
            for (int i = 0; i < 2; i++) {
                size_t r = row0 + wm + i * 16 + (lane >> 2);
                unsigned h, l;
                splitbf2(acc[i][j][0] + bb.x, acc[i][j][1] + bb.y, h, l);
                Ohi[r * 512 + (c >> 1)] = h;  Olo[r * 512 + (c >> 1)] = l;
                splitbf2(acc[i][j][2] + bb.x, acc[i][j][3] + bb.y, h, l);
                Ohi[(r + 8) * 512 + (c >> 1)] = h;  Olo[(r + 8) * 512 + (c >> 1)] = l;
            }
        }
    } else {
        #pragma unroll
        for (int j = 0; j < 8; j++) {
            int c = col0 + wn + j * 8 + (lane & 3) * 2;
            float2 bb = *(const float2*)&bias[c];
            #pragma unroll
            for (int i = 0; i < 2; i++) {
                size_t r = row0 + wm + i * 16 + (lane >> 2);
                float2 o0 = {acc[i][j][0] + bb.x, acc[i][j][1] + bb.y};
                float2 o1 = {acc[i][j][2] + bb.x, acc[i][j][3] + bb.y};
                *(float2*)&gv[r * DMODEL + c]       = o0;
                *(float2*)&gv[(r + 8) * DMODEL + c] = o1;
            }
        }
    }
}

// ---------------------------------------------------------------------------
// O projection: A = pctx0 + pctx1, cp.async 3-stage, 3 streams.
// ---------------------------------------------------------------------------
__global__ __launch_bounds__(256, 2)
void gemm_o_tf32(const float* __restrict__ pctx, const float* __restrict__ W,
                 const float* __restrict__ bias, float* __restrict__ C) {
    extern __shared__ float osm[];
    float* As0 = osm;
    float* As1 = osm + OP_AS;
    float* Ws2 = osm + 2 * OP_AS;
    const int tid = threadIdx.x, lane = tid & 31, warp = tid >> 5;
    const int wm = (warp & 3) * 32, wn = (warp >> 2) * 64;
    const int row0 = blockIdx.y * 128, col0 = blockIdx.x * 128;
    const int ntiles = DMODEL / 16;

    auto prefetch = [&](int t) {
        int s = t % OPSTG;
        int k0 = t * 16;
        #pragma unroll
        for (int l = 0; l < 2; l++) {
            int c = tid + l * 256, r = c >> 2, qd = (c & 3) * 4;
            size_t offA = (size_t)(row0 + r) * DMODEL + k0 + qd;
            cpasync16(&As0[s*2560 + r*20 + qd], &pctx[offA]);
            cpasync16(&As1[s*2560 + r*20 + qd], &pctx[offA + PS]);
            cpasync16(&Ws2[s*2560 + r*20 + qd], &W[(size_t)(col0+r)*DMODEL + k0 + qd]);
        }
        asm volatile("cp.async.commit_group;");
    };
    #pragma unroll
    for (int t = 0; t < OPSTG - 1; t++) prefetch(t);

    float acc[2][8][4] = {};
    for (int t = 0; t < ntiles; t++) {
        int s = t % OPSTG;
        asm volatile("cp.async.wait_group %0;" :: "n"(OPSTG - 2));
        __syncthreads();
        const float* A0 = &As0[s*2560];
        const float* A1 = &As1[s*2560];
        const float* Wp = &Ws2[s*2560];
        #pragma unroll
        for (int kk = 0; kk < 16; kk += 8) {
            const int kr = kk + (lane & 3), m0 = wm + (lane >> 2);
            unsigned af[2][4];
            #pragma unroll
            for (int i = 0; i < 2; i++) {
                int r0 = (m0 + i*16) * 20, r1 = (m0 + i*16 + 8) * 20;
                af[i][0] = __float_as_uint(A0[r0 + kr]   + A1[r0 + kr]);
                af[i][1] = __float_as_uint(A0[r1 + kr]   + A1[r1 + kr]);
                af[i][2] = __float_as_uint(A0[r0 + kr+4] + A1[r0 + kr+4]);
                af[i][3] = __float_as_uint(A0[r1 + kr+4] + A1[r1 + kr+4]);
            }
            #pragma unroll
            for (int j = 0; j < 8; j++) {
                int nb = wn + j * 8 + (lane >> 2);
                unsigned bf[2] = {__float_as_uint(Wp[nb*20 + kr]),
                                  __float_as_uint(Wp[nb*20 + kr+4])};
                mma8(acc[0][j], af[0], bf);
                mma8(acc[1][j], af[1], bf);
            }
        }
        __syncthreads();
        if (t + OPSTG - 1 < ntiles) prefetch(t + OPSTG - 1);
        else asm volatile("cp.async.commit_group;");
    }
    #pragma unroll
    for (int j = 0; j < 8; j++) {
        int c = col0 + wn + j * 8 + (lane & 3) * 2;
        float2 bb = *(const float2*)&bias[c];
        #pragma unroll
        for (int i = 0; i < 2; i++) {
            size_t r = row0 + wm + i * 16 + (lane >> 2);
            float2 o0 = {acc[i][j][0] + bb.x, acc[i][j][1] + bb.y};
            float2 o1 = {acc[i][j][2] + bb.x, acc[i][j][3] + bb.y};
            *(float2*)&C[r * DMODEL + c]       = o0;
            *(float2*)&C[(r + 8) * DMODEL + c] = o1;
        }
    }
}

// ---------------------------------------------------------------------------
// Fused scores (3xBF16) from PREPACKED gq/gk + mask + exp -> unnorm P + rowsums.
// ---------------------------------------------------------------------------
__global__ __launch_bounds__(256, 2)
void scores_exp(const unsigned* __restrict__ opk, const int* __restrict__ mask,
                float* __restrict__ attn, float* __restrict__ partial) {
    extern __shared__ unsigned dsm[];
    unsigned* Qh = dsm;                    // [128][36]
    unsigned* Ql = Qh + 128*36;
    unsigned* Kh = Ql + 128*36;
    unsigned* Kl = Kh + 128*36;
    float* sums = (float*)(Kl + 128*36);

    const int tid = threadIdx.x, lane = tid & 31, warp = tid >> 5;
    const int wm = (warp & 3) * 32, wn = (warp >> 2) * 64, kq = lane & 3;
    const int bh_i = blockIdx.x, b = bh_i >> 4, h = bh_i & 15;
    const int c0 = blockIdx.y * 128, q0 = blockIdx.z * 128;
    const unsigned* Qhi = opk;
    const unsigned* Qlo = opk + PKA;
    const unsigned* Khi = opk + 2 * PKA;
    const unsigned* Klo = opk + 3 * PKA;
    const int hoff = h * 32;

    #pragma unroll
    for (int l = 0; l < 4; l++) {
        int idx = tid + l * 256, r = idx >> 3, kp4 = (idx & 7) * 4;
        size_t qoff = (size_t)(b * SEQ + q0 + r) * 512 + hoff + kp4;
        size_t koff = (size_t)(b * SEQ + c0 + r) * 512 + hoff + kp4;
        cpasync16(&Qh[r*36 + kp4], &Qhi[qoff]);
        cpasync16(&Ql[r*36 + kp4], &Qlo[qoff]);
        cpasync16(&Kh[r*36 + kp4], &Khi[koff]);
        cpasync16(&Kl[r*36 + kp4], &Klo[koff]);
    }
    asm volatile("cp.async.commit_group;");
    asm volatile("cp.async.wait_group 0;");
    __syncthreads();

    float acc[2][8][4] = {};
    #pragma unroll
    for (int kk = 0; kk < 32; kk += 8) {
        unsigned ah[2][4], al[2][4];
        #pragma unroll
        for (int i = 0; i < 2; i++) {
            int m0 = wm + i * 16 + (lane >> 2);
            ah[i][0] = Qh[m0*36 + kk+kq];     ah[i][1] = Qh[(m0+8)*36 + kk+kq];
            ah[i][2] = Qh[m0*36 + kk+kq+4];   ah[i][3] = Qh[(m0+8)*36 + kk+kq+4];
            al[i][0] = Ql[m0*36 + kk+kq];     al[i][1] = Ql[(m0+8)*36 + kk+kq];
            al[i][2] = Ql[m0*36 + kk+kq+4];   al[i][3] = Ql[(m0+8)*36 + kk+kq+4];
        }
        #pragma unroll
        for (int j = 0; j < 8; j++) {
            int nb = wn + j * 8 + (lane >> 2);
            unsigned bh2[2] = {Kh[nb*36 + kk+kq], Kh[nb*36 + kk+kq+4]};
            unsigned bl2[2] = {Kl[nb*36 + kk+kq], Kl[nb*36 + kk+kq+4]};
            #pragma unroll
            for (int i = 0; i < 2; i++) {
                mma16(acc[i][j], al[i], bh2);
                mma16(acc[i][j], ah[i], bl2);
                mma16(acc[i][j], ah[i], bh2);
            }
        }
    }

    const int* mrow = mask + (size_t)b * SEQ * SEQ;
    float* out = attn + (size_t)bh_i * SEQ * SEQ;
    float rs[2][2] = {};
    #pragma unroll
    for (int j = 0; j < 8; j++) {
        int c = c0 + wn + j * 8 + (lane & 3) * 2;
        #pragma unroll
        for (int i = 0; i < 2; i++) {
            size_t r = q0 + wm + i * 16 + (lane >> 2);
            int2 m0v = *(const int2*)&mrow[r * SEQ + c];
            int2 m1v = *(const int2*)&mrow[(r + 8) * SEQ + c];
            float2 o0, o1;
            o0.x = m0v.x ? __expf(acc[i][j][0] * 0.125f) : 0.f;
            o0.y = m0v.y ? __expf(acc[i][j][1] * 0.125f) : 0.f;
            o1.x = m1v.x ? __expf(acc[i][j][2] * 0.125f) : 0.f;
            o1.y = m1v.y ? __expf(acc[i][j][3] * 0.125f) : 0.f;
            __stcs((float2*)&out[r * SEQ + c],       o0);
            __stcs((float2*)&out[(r + 8) * SEQ + c], o1);
            rs[i][0] += o0.x + o0.y;
            rs[i][1] += o1.x + o1.y;
        }
    }
    #pragma unroll
    for (int i = 0; i < 2; i++)
        #pragma unroll
        for (int hh = 0; hh < 2; hh++) {
            float v = rs[i][hh];
            v += __shfl_xor_sync(0xffffffffu, v, 1);
            v += __shfl_xor_sync(0xffffffffu, v, 2);
            if ((lane & 3) == 0)
                sums[(warp >> 2) * 128 + wm + i * 16 + hh * 8 + (lane >> 2)] = v;
        }
    __syncthreads();
    if (tid < 128) {
        float tot = sums[tid] + sums[128 + tid];
        partial[((size_t)bh_i * SEQ + q0 + tid) * NKT + blockIdx.y] = tot;
    }
}

// ---------------------------------------------------------------------------
// Fused PV (tf32, split-K=2), cp.async 3-stage, 4 CTAs/SM.
// ---------------------------------------------------------------------------
__global__ __launch_bounds__(256, 4)
void pv_norm(float* __restrict__ attn, const float* __restrict__ gv,
             const float* __restrict__ partial, float* __restrict__ pctx) {
    extern __shared__ float psm[];
    float* Ps    = psm;
    float* Vs    = psm + PV_PS;
    float* inv_s = psm + PV_PS + PV_VS;

    const int tid = threadIdx.x, lane = tid & 31, warp = tid >> 5;
    const int wm = (warp & 3) * 32, wn = (warp >> 2) * 32;
    const int bh_i = blockIdx.z, b = bh_i >> 4, h = bh_i & 15;
    float* P = attn + (size_t)bh_i * SEQ * SEQ;
    const float* V = gv + (size_t)b * SEQ * DMODEL + h * DHEAD;
    float* Cc = pctx + (size_t)blockIdx.x * PS
                     + (size_t)b * SEQ * DMODEL + h * DHEAD;
    const int q0 = blockIdx.y * 128;
    const int kbase = blockIdx.x * (SEQ / SPLITK);
    const int ntiles = (SEQ / SPLITK) / 16;

    auto prefetch = [&](int t) {
        int s = t % PVSTG;
        int k0 = kbase + t * 16;
        #pragma unroll
        for (int l = 0; l < 2; l++) {
            int c = tid + l * 256, r = c >> 2, qd = (c & 3) * 4;
            cpasync16(&Ps[s*2560 + r*20 + qd], &P[(size_t)(q0+r)*SEQ + k0 + qd]);
        }
        {
            int kk = tid >> 4, n = (tid & 15) * 4;
            cpasync16(&Vs[s*1152 + kk*72 + n], &V[(size_t)(k0+kk)*DMODEL + n]);
        }
        asm volatile("cp.async.commit_group;");
    };
    #pragma unroll
    for (int t = 0; t < PVSTG - 1; t++) prefetch(t);

    if (tid < 128) {
        const float4* pp = (const float4*)&partial[((size_t)bh_i * SEQ + q0 + tid) * NKT];
        float4 p0 = pp[0], p1 = pp[1], p2 = pp[2], p3 = pp[3];
        float s = ((p0.x + p0.y) + (p0.z + p0.w)) + ((p1.x + p1.y) + (p1.z + p1.w))
                + ((p2.x + p2.y) + (p2.z + p2.w)) + ((p3.x + p3.y) + (p3.z + p3.w));
        inv_s[tid] = 1.0f / s;
    }

    float acc[2][4][4] = {};
    for (int t = 0; t < ntiles; t++) {
        int s = t % PVSTG;
        asm volatile("cp.async.wait_group %0;" :: "n"(PVSTG - 2));
        __syncthreads();
        const float* Pp = &Ps[s*2560];
        const float* Vp = &Vs[s*1152];
        #pragma unroll
        for (int kk = 0; kk < 16; kk += 8) {
            const int kr = kk + (lane & 3), m0 = wm + (lane >> 2);
            unsigned af[2][4];
            #pragma unroll
            for (int i = 0; i < 2; i++) {
                af[i][0] = __float_as_uint(Pp[(m0+i*16)*20 + kr]);
                af[i][1] = __float_as_uint(Pp[(m0+i*16+8)*20 + kr]);
                af[i][2] = __float_as_uint(Pp[(m0+i*16)*20 + kr+4]);
                af[i][3] = __float_as_uint(Pp[(m0+i*16+8)*20 + kr+4]);
            }
            #pragma unroll
            for (int j = 0; j < 4; j++) {
                int nb = wn + j * 8 + (lane >> 2);
                unsigned bfr[2] = {__float_as_uint(Vp[kr*72 + nb]),
                                   __float_as_uint(Vp[(kr+4)*72 + nb])};
                mma8(acc[0][j], af[0], bfr);
                mma8(acc[1][j], af[1], bfr);
            }
        }
        {
            int k0 = kbase + t * 16;
            #pragma unroll
            for (int l = 0; l < 2; l++) {
                int c = tid + l * 256, r = c >> 2, qd = (c & 3) * 4;
                float4 a4 = *(const float4*)&Pp[r*20 + qd];
                float sc = inv_s[r];
                a4.x *= sc; a4.y *= sc; a4.z *= sc; a4.w *= sc;
                __stcs((float4*)&P[(size_t)(q0+r)*SEQ + k0 + qd], a4);
            }
        }
        __syncthreads();
        if (t + PVSTG - 1 < ntiles) prefetch(t + PVSTG - 1);
        else asm volatile("cp.async.commit_group;");
    }
    #pragma unroll
    for (int j = 0; j < 4; j++) {
        int c = wn + j * 8 + (lane & 3) * 2;
        #pragma unroll
        for (int i = 0; i < 2; i++) {
            int rl = wm + i * 16 + (lane >> 2);
            float sc0 = inv_s[rl], sc1 = inv_s[rl + 8];
            size_t r = q0 + rl;
            float2 o0 = {acc[i][j][0] * sc0, acc[i][j][1] * sc0};
            float2 o1 = {acc[i][j][2] * sc1, acc[i][j][3] * sc1};
            *(float2*)&Cc[r * DMODEL + c]       = o0;
            *(float2*)&Cc[(r + 8) * DMODEL + c] = o1;
        }
    }
}

// ---------------------------------------------------------------------------
// Residual + LayerNorm.
// ---------------------------------------------------------------------------
__global__ void ln_kernel(const float* __restrict__ resid,
                          const float* __restrict__ x,
                          const float* __restrict__ gamma,
                          const float* __restrict__ beta,
                          float* __restrict__ out) {
    const size_t row = blockIdx.x;
    const float4* xr = reinterpret_cast<const float4*>(x + row * DMODEL);
    const float4* rr = reinterpret_cast<const float4*>(resid + row * DMODEL);
    const int t = threadIdx.x;
    __shared__ float sred[8];

    float4 a = rr[t], bv = xr[t];
    float4 v = {a.x + bv.x, a.y + bv.y, a.z + bv.z, a.w + bv.w};
    float s = v.x + v.y + v.z + v.w;
    #pragma unroll
    for (int o = 16; o > 0; o >>= 1) s += __shfl_xor_sync(0xffffffffu, s, o);
    if ((t & 31) == 0) sred[t >> 5] = s;
    __syncthreads();
    float tot = 0.f;
    #pragma unroll
    for (int i = 0; i < 8; i++) tot += sred[i];
    const float mu = tot * (1.0f / DMODEL);
    __syncthreads();

    float dx = v.x - mu, dy = v.y - mu, dz = v.z - mu, dw = v.w - mu;
    float sq = dx*dx + dy*dy + dz*dz + dw*dw;
    #pragma unroll
    for (int o = 16; o > 0; o >>= 1) sq += __shfl_xor_sync(0xffffffffu, sq, o);
    if ((t & 31) == 0) sred[t >> 5] = sq;
    __syncthreads();
    float tot2 = 0.f;
    #pragma unroll
    for (int i = 0; i < 8; i++) tot2 += sred[i];
    const float inv = rsqrtf(tot2 * (1.0f / DMODEL) + 1e-5f);

    float4 g = reinterpret_cast<const float4*>(gamma)[t];
    float4 be = reinterpret_cast<const float4*>(beta)[t];
    float4 o;
    o.x = dx * inv * g.x + be.x;
    o.y = dy * inv * g.y + be.y;
    o.z = dz * inv * g.z + be.z;
    o.w = dw * inv * g.w + be.w;
    reinterpret_cast<float4*>(out + row * DMODEL)[t] = o;
}

// ---------------------------------------------------------------------------
extern "C" void kernel_launch(void* const* d_in, const int* in_sizes, int n_in,
                              void* d_out, int out_size) {
    const float* q     = (const float*)d_in[0];
    const float* k     = (const float*)d_in[1];
    const float* v     = (const float*)d_in[2];
    const int*   mask  = (const int*)  d_in[3];
    const float* wq    = (const float*)d_in[4];
    const float* bq    = (const float*)d_in[5];
    const float* wk    = (const float*)d_in[6];
    const float* bk    = (const float*)d_in[7];
    const float* wv    = (const float*)d_in[8];
    const float* bv    = (const float*)d_in[9];
    const float* wo    = (const float*)d_in[10];
    const float* bo    = (const float*)d_in[11];
    const float* gamma = (const float*)d_in[12];
    const float* beta  = (const float*)d_in[13];

    float* out  = (float*)d_out;
    float* attn = out + ATT_OFF;

    void* sp = nullptr;
    cudaGetSymbolAddress(&sp, g_scratch);
    float* gv      = (float*)sp;
    float* go      = gv + PS;
    float* pctx    = go + PS;                 // SPLITK x PS
    float* partial = pctx + SPLITK * PS;
    unsigned* ipk  = (unsigned*)(partial + PARTIAL_SZ);   // q,k,v hi/lo (6*PKA)
    unsigned* wpk  = ipk + 6 * PKA;                        // wq,wk,wv hi/lo (6*PKW)
    unsigned* opk  = wpk + 6 * PKW;                        // gq,gk hi/lo (4*PKA)

    cudaFuncSetAttribute(scores_exp,   cudaFuncAttributeMaxDynamicSharedMemorySize, SC_SMEM);
    cudaFuncSetAttribute(pv_norm,      cudaFuncAttributeMaxDynamicSharedMemorySize, PV_SMEM);
    cudaFuncSetAttribute(gemm_o_tf32,  cudaFuncAttributeMaxDynamicSharedMemorySize, OP_SMEM);
    cudaFuncSetAttribute(gemm_proj_pk, cudaFuncAttributeMaxDynamicSharedMemorySize, QK_SMEM);

    dim3 gPre((unsigned)((PKA / 2 + 255) / 256), 6);
    prepack_all<<<gPre, 256>>>(q, k, v, wq, wk, wv, ipk, wpk);

    dim3 gProj3(DMODEL / 128, MROWS / 128, 3);          // (8, 32, 3): q, k, v
    gemm_proj_pk<<<gProj3, 256, QK_SMEM>>>(ipk, wpk, bq, bk, bv, opk, gv);

    dim3 gScores(BATCH * NHEADS, NKT, SEQ / 128);       // (32, 16, 16)
    scores_exp<<<gScores, 256, SC_SMEM>>>(opk, mask, attn, partial);

    dim3 gPV(SPLITK, SEQ / 128, BATCH * NHEADS);        // (2, 16, 32)
    pv_norm<<<gPV, 256, PV_SMEM>>>(attn, gv, partial, pctx);

    dim3 gProj(DMODEL / 128, MROWS / 128);              // (8, 32)
    gemm_o_tf32<<<gProj, 256, OP_SMEM>>>(pctx, wo, bo, go);

    ln_kernel<<<MROWS, 256>>>(q, go, gamma, beta, out);
}

// round 13
// speedup vs baseline: 1.0493x; 1.0493x over previous
#include <cuda_runtime.h>
#include <cuda_bf16.h>
#include <cuda_fp16.h>
#include <math.h>

#define BATCH 2
#define SEQ   2048
#define DMODEL 1024
#define NHEADS 16
#define DHEAD  64
#define MROWS (BATCH*SEQ)                    // 4096
#define ATT_OFF ((size_t)BATCH*SEQ*DMODEL)
#define NKT 16
#define SPLITK 2
#define OPSTG 3
#define QKSTG 4
#define VPSTG 4
#define PV16STG 3

#define PS   ((size_t)MROWS * DMODEL)        // 4M floats
#define PKA  ((size_t)MROWS * 512)           // 2M u32 kpairs
#define PKW  ((size_t)DMODEL * 512)          // 0.5M u32
#define PARTIAL_SZ ((size_t)BATCH * NHEADS * SEQ * NKT)
#define P16_SZ ((size_t)BATCH * NHEADS * SEQ * (SEQ/2))   // 64Mi u32
#define GV16_SZ ((size_t)(MROWS/2) * DMODEL)              // 2Mi u32

// gv, go, pctx(2), partial, ipk(4*PKA), wpk(4*PKW), opk(4*PKA), gv16, p16
__device__ float g_scratch[4ull * PS + PARTIAL_SZ + 8ull * PKA + 4ull * PKW
                           + GV16_SZ + P16_SZ];

// scores smem: Qh/Ql/Kh/Kl [128][36] u32 + sums[2][128]
#define SC_SMEM (4 * 128 * 36 * 4 + 256 * 4)
// pv16 smem: P stages [3][128][20] u32 + V stages [3][16][68] u32 + inv_s[128]
#define PV16_PS (PV16STG * 128 * 20)
#define PV16_VS (PV16STG * 16 * 68)
#define PV16_SMEM ((PV16_PS + PV16_VS + 128) * 4)
// vproj smem
#define VP_AS   (VPSTG * 128 * 20)
#define VP_SMEM (2 * VP_AS * 4)
// oproj smem
#define OP_AS   (OPSTG * 128 * 20)
#define OP_SMEM (3 * OP_AS * 4)
// qk smem: 4 arrays x QKSTG stages x [128][12]
#define QK_ARR  (QKSTG * 128 * 12)
#define QK_SMEM (4 * QK_ARR * 4)

// ---------------------------------------------------------------------------
__device__ __forceinline__ void mma8(float* d, const unsigned* a, const unsigned* b) {
    asm volatile(
        "mma.sync.aligned.m16n8k8.row.col.f32.tf32.tf32.f32 "
        "{%0,%1,%2,%3}, {%4,%5,%6,%7}, {%8,%9}, {%0,%1,%2,%3};"
        : "+f"(d[0]), "+f"(d[1]), "+f"(d[2]), "+f"(d[3])
        : "r"(a[0]), "r"(a[1]), "r"(a[2]), "r"(a[3]), "r"(b[0]), "r"(b[1]));
}
__device__ __forceinline__ void mma16(float* d, const unsigned* a, const unsigned* b) {
    asm volatile(
        "mma.sync.aligned.m16n8k16.row.col.f32.bf16.bf16.f32 "
        "{%0,%1,%2,%3}, {%4,%5,%6,%7}, {%8,%9}, {%0,%1,%2,%3};"
        : "+f"(d[0]), "+f"(d[1]), "+f"(d[2]), "+f"(d[3])
        : "r"(a[0]), "r"(a[1]), "r"(a[2]), "r"(a[3]), "r"(b[0]), "r"(b[1]));
}
__device__ __forceinline__ void mma16h(float* d, const unsigned* a, const unsigned* b) {
    asm volatile(
        "mma.sync.aligned.m16n8k16.row.col.f32.f16.f16.f32 "
        "{%0,%1,%2,%3}, {%4,%5,%6,%7}, {%8,%9}, {%0,%1,%2,%3};"
        : "+f"(d[0]), "+f"(d[1]), "+f"(d[2]), "+f"(d[3])
        : "r"(a[0]), "r"(a[1]), "r"(a[2]), "r"(a[3]), "r"(b[0]), "r"(b[1]));
}
__device__ __forceinline__ void splitbf2(float x, float y, unsigned& hi, unsigned& lo) {
    __nv_bfloat16 hx = __float2bfloat16_rn(x);
    __nv_bfloat16 hy = __float2bfloat16_rn(y);
    __nv_bfloat16 lx = __float2bfloat16_rn(x - __bfloat162float(hx));
    __nv_bfloat16 ly = __float2bfloat16_rn(y - __bfloat162float(hy));
    hi = (unsigned)__bfloat16_as_ushort(hx) | ((unsigned)__bfloat16_as_ushort(hy) << 16);
    lo = (unsigned)__bfloat16_as_ushort(lx) | ((unsigned)__bfloat16_as_ushort(ly) << 16);
}
__device__ __forceinline__ unsigned packh2(float x, float y) {
    __half2 h = __floats2half2_rn(x, y);
    return *reinterpret_cast<unsigned*>(&h);
}
__device__ __forceinline__ float2 unpackh2(unsigned u) {
    __half2 h = *reinterpret_cast<__half2*>(&u);
    return __half22float2(h);
}
__device__ __forceinline__ void cpasync16(void* sm, const void* gm) {
    unsigned a = (unsigned)__cvta_generic_to_shared(sm);
    asm volatile("cp.async.cg.shared.global [%0], [%1], 16;" :: "r"(a), "l"(gm));
}

// ---------------------------------------------------------------------------
// Prepack q,k,wq,wk -> bf16 (hi,lo) kpair arrays. grid.y selects tensor.
// ---------------------------------------------------------------------------
__global__ void prepack_all(const float* __restrict__ q, const float* __restrict__ k,
                            const float* __restrict__ wq, const float* __restrict__ wk,
                            unsigned* __restrict__ ipk, unsigned* __restrict__ wpk) {
    const int z = blockIdx.y;
    const int i = blockIdx.x * 256 + threadIdx.x;
    const float* src;
    unsigned *hi, *lo;
    int half;
    if (z < 2) {
        src = z ? k : q;
        hi = ipk + (size_t)z * 2 * PKA; lo = hi + PKA;
        half = (int)(PKA / 2);
    } else {
        src = (z == 2) ? wq : wk;
        hi = wpk + (size_t)(z - 2) * 2 * PKW; lo = hi + PKW;
        half = (int)(PKW / 2);
    }
    if (i < half) {
        float4 x = ((const float4*)src)[i];
        unsigned h0, l0, h1, l1;
        splitbf2(x.x, x.y, h0, l0);
        splitbf2(x.z, x.w, h1, l1);
        ((uint2*)hi)[i] = make_uint2(h0, h1);
        ((uint2*)lo)[i] = make_uint2(l0, l1);
    }
}

// ---------------------------------------------------------------------------
// Pack gv (fp32) -> gv16 fp16 k-pair format: u32[t][n] = (V[2t][n], V[2t+1][n]).
// ---------------------------------------------------------------------------
__global__ void pack_v16(const float* __restrict__ gv, unsigned* __restrict__ gv16) {
    size_t i = (size_t)blockIdx.x * 256 + threadIdx.x;   // (MROWS/2)*(DMODEL/4)
    size_t t = i >> 8;
    int n4 = (int)(i & 255) * 4;
    float4 a = *(const float4*)&gv[(2 * t) * DMODEL + n4];
    float4 b = *(const float4*)&gv[(2 * t + 1) * DMODEL + n4];
    uint4 o;
    o.x = packh2(a.x, b.x); o.y = packh2(a.y, b.y);
    o.z = packh2(a.z, b.z); o.w = packh2(a.w, b.w);
    *(uint4*)&gv16[t * DMODEL + n4] = o;
}

// ---------------------------------------------------------------------------
// q+k projections from PREPACKED operands, 3xBF16, cp.async 4-stage.
// ---------------------------------------------------------------------------
__global__ __launch_bounds__(256, 2)
void gemm_qk_pk(const unsigned* __restrict__ apk, const unsigned* __restrict__ wpk,
                const float* __restrict__ bq, const float* __restrict__ bk,
                unsigned* __restrict__ outpk) {
    extern __shared__ unsigned qsm[];
    unsigned* Ah = qsm;
    unsigned* Al = qsm + QK_ARR;
    unsigned* Wh = qsm + 2 * QK_ARR;
    unsigned* Wl = qsm + 3 * QK_ARR;
    const int z = blockIdx.z;
    const unsigned* Ahi = apk + (size_t)z * 2 * PKA;
    const unsigned* Alo = Ahi + PKA;
    const unsigned* Whi = wpk + (size_t)z * 2 * PKW;
    const unsigned* Wlo = Whi + PKW;
    unsigned* Ohi = outpk + (size_t)z * 2 * PKA;
    unsigned* Olo = Ohi + PKA;
    const float* bias = z ? bk : bq;

    const int tid = threadIdx.x, lane = tid & 31, warp = tid >> 5;
    const int wm = (warp & 3) * 32, wn = (warp >> 2) * 64, kq = lane & 3;
    const int row0 = blockIdx.y * 128, col0 = blockIdx.x * 128;
    const int ntiles = 512 / 8;

    const int pr = tid >> 1, pk4 = (tid & 1) * 4;
    auto prefetch = [&](int t) {
        int s = t & (QKSTG - 1);
        int kp0 = t * 8;
        cpasync16(&Ah[s*1536 + pr*12 + pk4], &Ahi[(size_t)(row0+pr)*512 + kp0 + pk4]);
        cpasync16(&Al[s*1536 + pr*12 + pk4], &Alo[(size_t)(row0+pr)*512 + kp0 + pk4]);
        cpasync16(&Wh[s*1536 + pr*12 + pk4], &Whi[(size_t)(col0+pr)*512 + kp0 + pk4]);
        cpasync16(&Wl[s*1536 + pr*12 + pk4], &Wlo[(size_t)(col0+pr)*512 + kp0 + pk4]);
        asm volatile("cp.async.commit_group;");
    };
    #pragma unroll
    for (int t = 0; t < QKSTG - 1; t++) prefetch(t);

    float acc[2][8][4] = {};
    for (int t = 0; t < ntiles; t++) {
        int s = t & (QKSTG - 1);
        asm volatile("cp.async.wait_group %0;" :: "n"(QKSTG - 2));
        __syncthreads();
        const unsigned* Ahp = &Ah[s*1536];
        const unsigned* Alp = &Al[s*1536];
        const unsigned* Whp = &Wh[s*1536];
        const unsigned* Wlp = &Wl[s*1536];
        unsigned ah[2][4], al[2][4];
        #pragma unroll
        for (int i = 0; i < 2; i++) {
            int m0 = wm + i * 16 + (lane >> 2);
            ah[i][0] = Ahp[m0*12 + kq];     ah[i][1] = Ahp[(m0+8)*12 + kq];
            ah[i][2] = Ahp[m0*12 + kq+4];   ah[i][3] = Ahp[(m0+8)*12 + kq+4];
            al[i][0] = Alp[m0*12 + kq];     al[i][1] = Alp[(m0+8)*12 + kq];
            al[i][2] = Alp[m0*12 + kq+4];   al[i][3] = Alp[(m0+8)*12 + kq+4];
        }
        #pragma unroll
        for (int j = 0; j < 8; j++) {
            int nb = wn + j * 8 + (lane >> 2);
            unsigned bh2[2] = {Whp[nb*12 + kq], Whp[nb*12 + kq+4]};
            unsigned bl2[2] = {Wlp[nb*12 + kq], Wlp[nb*12 + kq+4]};
            #pragma unroll
            for (int i = 0; i < 2; i++) {
                mma16(acc[i][j], al[i], bh2);
                mma16(acc[i][j], ah[i], bl2);
                mma16(acc[i][j], ah[i], bh2);
            }
        }
        __syncthreads();
        if (t + QKSTG - 1 < ntiles) prefetch(t + QKSTG - 1);
        else asm volatile("cp.async.commit_group;");
    }
    #pragma unroll
    for (int j = 0; j < 8; j++) {
        int c = col0 + wn + j * 8 + (lane & 3) * 2;
        float2 bb = *(const float2*)&bias[c];
        #pragma unroll
        for (int i = 0; i < 2; i++) {
            size_t r = row0 + wm + i * 16 + (lane >> 2);
            unsigned h, l;
            splitbf2(acc[i][j][0] + bb.x, acc[i][j][1] + bb.y, h, l);
            Ohi[r * 512 + (c >> 1)] = h;  Olo[r * 512 + (c >> 1)] = l;
            splitbf2(acc[i][j][2] + bb.x, acc[i][j][3] + bb.y, h, l);
            Ohi[(r + 8) * 512 + (c >> 1)] = h;  Olo[(r + 8) * 512 + (c >> 1)] = l;
        }
    }
}

// ---------------------------------------------------------------------------
// V projection (1xTF32), cp.async 4-stage, raw fp32 smem tiles.
// ---------------------------------------------------------------------------
__global__ __launch_bounds__(256, 2)
void gemm_nt_tf32(const float* __restrict__ A, const float* __restrict__ W,
                  const float* __restrict__ bias, float* __restrict__ C) {
    extern __shared__ float vsm[];
    float* As2 = vsm;
    float* Ws2 = vsm + VP_AS;
    const int tid = threadIdx.x, lane = tid & 31, warp = tid >> 5;
    const int wm = (warp & 3) * 32, wn = (warp >> 2) * 64;
    const int row0 = blockIdx.y * 128, col0 = blockIdx.x * 128;
    const int ntiles = DMODEL / 16;

    auto prefetch = [&](int t) {
        int s = t & (VPSTG - 1);
        int k0 = t * 16;
        #pragma unroll
        for (int l = 0; l < 2; l++) {
            int c = tid + l * 256, r = c >> 2, qd = (c & 3) * 4;
            cpasync16(&As2[s*2560 + r*20 + qd], &A[(size_t)(row0+r)*DMODEL + k0 + qd]);
            cpasync16(&Ws2[s*2560 + r*20 + qd], &W[(size_t)(col0+r)*DMODEL + k0 + qd]);
        }
        asm volatile("cp.async.commit_group;");
    };
    #pragma unroll
    for (int t = 0; t < VPSTG - 1; t++) prefetch(t);

    float acc[2][8][4] = {};
    for (int t = 0; t < ntiles; t++) {
        int s = t & (VPSTG - 1);
        asm volatile("cp.async.wait_group %0;" :: "n"(VPSTG - 2));
        __syncthreads();
        const float* Ap = &As2[s*2560];
        const float* Wp = &Ws2[s*2560];
        #pragma unroll
        for (int kk = 0; kk < 16; kk += 8) {
            const int kr = kk + (lane & 3), m0 = wm + (lane >> 2);
            unsigned af[2][4];
            #pragma unroll
            for (int i = 0; i < 2; i++) {
                af[i][0] = __float_as_uint(Ap[(m0+i*16)*20 + kr]);
                af[i][1] = __float_as_uint(Ap[(m0+i*16+8)*20 + kr]);
                af[i][2] = __float_as_uint(Ap[(m0+i*16)*20 + kr+4]);
                af[i][3] = __float_as_uint(Ap[(m0+i*16+8)*20 + kr+4]);
            }
            #pragma unroll
            for (int j = 0; j < 8; j++) {
                int nb = wn + j * 8 + (lane >> 2);
                unsigned bf[2] = {__float_as_uint(Wp[nb*20 + kr]),
                                  __float_as_uint(Wp[nb*20 + kr+4])};
                mma8(acc[0][j], af[0], bf);
                mma8(acc[1][j], af[1], bf);
            }
        }
        __syncthreads();
        if (t + VPSTG - 1 < ntiles) prefetch(t + VPSTG - 1);
        else asm volatile("cp.async.commit_group;");
    }
    #pragma unroll
    for (int j = 0; j < 8; j++) {
        int c = col0 + wn + j * 8 + (lane & 3) * 2;
        float2 bb = *(const float2*)&bias[c];
        #pragma unroll
        for (int i = 0; i < 2; i++) {
            size_t r = row0 + wm + i * 16 + (lane >> 2);
            float2 o0 = {acc[i][j][0] + bb.x, acc[i][j][1] + bb.y};
            float2 o1 = {acc[i][j][2] + bb.x, acc[i][j][3] + bb.y};
            *(float2*)&C[r * DMODEL + c]       = o0;
            *(float2*)&C[(r + 8) * DMODEL + c] = o1;
        }
    }
}

// ---------------------------------------------------------------------------
// O projection: A = pctx0 + pctx1, cp.async 3-stage, 3 streams.
// ---------------------------------------------------------------------------
__global__ __launch_bounds__(256, 2)
void gemm_o_tf32(const float* __restrict__ pctx, const float* __restrict__ W,
                 const float* __restrict__ bias, float* __restrict__ C) {
    extern __shared__ float osm[];
    float* As0 = osm;
    float* As1 = osm + OP_AS;
    float* Ws2 = osm + 2 * OP_AS;
    const int tid = threadIdx.x, lane = tid & 31, warp = tid >> 5;
    const int wm = (warp & 3) * 32, wn = (warp >> 2) * 64;
    const int row0 = blockIdx.y * 128, col0 = blockIdx.x * 128;
    const int ntiles = DMODEL / 16;

    auto prefetch = [&](int t) {
        int s = t % OPSTG;
        int k0 = t * 16;
        #pragma unroll
        for (int l = 0; l < 2; l++) {
            int c = tid + l * 256, r = c >> 2, qd = (c & 3) * 4;
            size_t offA = (size_t)(row0 + r) * DMODEL + k0 + qd;
            cpasync16(&As0[s*2560 + r*20 + qd], &pctx[offA]);
            cpasync16(&As1[s*2560 + r*20 + qd], &pctx[offA + PS]);
            cpasync16(&Ws2[s*2560 + r*20 + qd], &W[(size_t)(col0+r)*DMODEL + k0 + qd]);
        }
        asm volatile("cp.async.commit_group;");
    };
    #pragma unroll
    for (int t = 0; t < OPSTG - 1; t++) prefetch(t);

    float acc[2][8][4] = {};
    for (int t = 0; t < ntiles; t++) {
        int s = t % OPSTG;
        asm volatile("cp.async.wait_group %0;" :: "n"(OPSTG - 2));
        __syncthreads();
        const float* A0 = &As0[s*2560];
        const float* A1 = &As1[s*2560];
        const float* Wp = &Ws2[s*2560];
        #pragma unroll
        for (int kk = 0; kk < 16; kk += 8) {
            const int kr = kk + (lane & 3), m0 = wm + (lane >> 2);
            unsigned af[2][4];
            #pragma unroll
            for (int i = 0; i < 2; i++) {
                int r0 = (m0 + i*16) * 20, r1 = (m0 + i*16 + 8) * 20;
                af[i][0] = __float_as_uint(A0[r0 + kr]   + A1[r0 + kr]);
                af[i][1] = __float_as_uint(A0[r1 + kr]   + A1[r1 + kr]);
                af[i][2] = __float_as_uint(A0[r0 + kr+4] + A1[r0 + kr+4]);
                af[i][3] = __float_as_uint(A0[r1 + kr+4] + A1[r1 + kr+4]);
            }
            #pragma unroll
            for (int j = 0; j < 8; j++) {
                int nb = wn + j * 8 + (lane >> 2);
                unsigned bf[2] = {__float_as_uint(Wp[nb*20 + kr]),
                                  __float_as_uint(Wp[nb*20 + kr+4])};
                mma8(acc[0][j], af[0], bf);
                mma8(acc[1][j], af[1], bf);
            }
        }
        __syncthreads();
        if (t + OPSTG - 1 < ntiles) prefetch(t + OPSTG - 1);
        else asm volatile("cp.async.commit_group;");
    }
    #pragma unroll
    for (int j = 0; j < 8; j++) {
        int c = col0 + wn + j * 8 + (lane & 3) * 2;
        float2 bb = *(const float2*)&bias[c];
        #pragma unroll
        for (int i = 0; i < 2; i++) {
            size_t r = row0 + wm + i * 16 + (lane >> 2);
            float2 o0 = {acc[i][j][0] + bb.x, acc[i][j][1] + bb.y};
            float2 o1 = {acc[i][j][2] + bb.x, acc[i][j][3] + bb.y};
            *(float2*)&C[r * DMODEL + c]       = o0;
            *(float2*)&C[(r + 8) * DMODEL + c] = o1;
        }
    }
}

// ---------------------------------------------------------------------------
// Fused scores (3xBF16) from PREPACKED gq/gk + mask + exp -> fp16 unnorm P
// + fp32 rowsum partials. grid (32 bh, NKT ktile, 16 qtile).
// ---------------------------------------------------------------------------
__global__ __launch_bounds__(256, 2)
void scores_exp(const unsigned* __restrict__ opk, const int* __restrict__ mask,
                unsigned* __restrict__ p16, float* __restrict__ partial) {
    extern __shared__ unsigned dsm[];
    unsigned* Qh = dsm;                    // [128][36]
    unsigned* Ql = Qh + 128*36;
    unsigned* Kh = Ql + 128*36;
    unsigned* Kl = Kh + 128*36;
    float* sums = (float*)(Kl + 128*36);

    const int tid = threadIdx.x, lane = tid & 31, warp = tid >> 5;
    const int wm = (warp & 3) * 32, wn = (warp >> 2) * 64, kq = lane & 3;
    const int bh_i = blockIdx.x, b = bh_i >> 4, h = bh_i & 15;
    const int c0 = blockIdx.y * 128, q0 = blockIdx.z * 128;
    const unsigned* Qhi = opk;
    const unsigned* Qlo = opk + PKA;
    const unsigned* Khi = opk + 2 * PKA;
    const unsigned* Klo = opk + 3 * PKA;
    const int hoff = h * 32;

    #pragma unroll
    for (int l = 0; l < 4; l++) {
        int idx = tid + l * 256, r = idx >> 3, kp4 = (idx & 7) * 4;
        size_t qoff = (size_t)(b * SEQ + q0 + r) * 512 + hoff + kp4;
        size_t koff = (size_t)(b * SEQ + c0 + r) * 512 + hoff + kp4;
        cpasync16(&Qh[r*36 + kp4], &Qhi[qoff]);
        cpasync16(&Ql[r*36 + kp4], &Qlo[qoff]);
        cpasync16(&Kh[r*36 + kp4], &Khi[koff]);
        cpasync16(&Kl[r*36 + kp4], &Klo[koff]);
    }
    asm volatile("cp.async.commit_group;");
    asm volatile("cp.async.wait_group 0;");
    __syncthreads();

    float acc[2][8][4] = {};
    #pragma unroll
    for (int kk = 0; kk < 32; kk += 8) {
        unsigned ah[2][4], al[2][4];
        #pragma unroll
        for (int i = 0; i < 2; i++) {
            int m0 = wm + i * 16 + (lane >> 2);
            ah[i][0] = Qh[m0*36 + kk+kq];     ah[i][1] = Qh[(m0+8)*36 + kk+kq];
            ah[i][2] = Qh[m0*36 + kk+kq+4];   ah[i][3] = Qh[(m0+8)*36 + kk+kq+4];
            al[i][0] = Ql[m0*36 + kk+kq];     al[i][1] = Ql[(m0+8)*36 + kk+kq];
            al[i][2] = Ql[m0*36 + kk+kq+4];   al[i][3] = Ql[(m0+8)*36 + kk+kq+4];
        }
        #pragma unroll
        for (int j = 0; j < 8; j++) {
            int nb = wn + j * 8 + (lane >> 2);
            unsigned bh2[2] = {Kh[nb*36 + kk+kq], Kh[nb*36 + kk+kq+4]};
            unsigned bl2[2] = {Kl[nb*36 + kk+kq], Kl[nb*36 + kk+kq+4]};
            #pragma unroll
            for (int i = 0; i < 2; i++) {
                mma16(acc[i][j], al[i], bh2);
                mma16(acc[i][j], ah[i], bl2);
                mma16(acc[i][j], ah[i], bh2);
            }
        }
    }

    const int* mrow = mask + (size_t)b * SEQ * SEQ;
    unsigned* out16 = p16 + (size_t)bh_i * SEQ * (SEQ / 2);
    float rs[2][2] = {};
    #pragma unroll
    for (int j = 0; j < 8; j++) {
        int c = c0 + wn + j * 8 + (lane & 3) * 2;
        int kp = c >> 1;
        #pragma unroll
        for (int i = 0; i < 2; i++) {
            size_t r = q0 + wm + i * 16 + (lane >> 2);
            int2 m0v = *(const int2*)&mrow[r * SEQ + c];
            int2 m1v = *(const int2*)&mrow[(r + 8) * SEQ + c];
            float2 o0, o1;
            o0.x = m0v.x ? __expf(acc[i][j][0] * 0.125f) : 0.f;
            o0.y = m0v.y ? __expf(acc[i][j][1] * 0.125f) : 0.f;
            o1.x = m1v.x ? __expf(acc[i][j][2] * 0.125f) : 0.f;
            o1.y = m1v.y ? __expf(acc[i][j][3] * 0.125f) : 0.f;
            out16[r * (SEQ/2) + kp]       = packh2(o0.x, o0.y);
            out16[(r + 8) * (SEQ/2) + kp] = packh2(o1.x, o1.y);
            rs[i][0] += o0.x + o0.y;
            rs[i][1] += o1.x + o1.y;
        }
    }
    #pragma unroll
    for (int i = 0; i < 2; i++)
        #pragma unroll
        for (int hh = 0; hh < 2; hh++) {
            float v = rs[i][hh];
            v += __shfl_xor_sync(0xffffffffu, v, 1);
            v += __shfl_xor_sync(0xffffffffu, v, 2);
            if ((lane & 3) == 0)
                sums[(warp >> 2) * 128 + wm + i * 16 + hh * 8 + (lane >> 2)] = v;
        }
    __syncthreads();
    if (tid < 128) {
        float tot = sums[tid] + sums[128 + tid];
        partial[((size_t)bh_i * SEQ + q0 + tid) * NKT + blockIdx.y] = tot;
    }
}

// ---------------------------------------------------------------------------
// Fused PV (f16 mma, split-K=2), cp.async 3-stage, BK=32 keys.
// Reads fp16 P + fp16 V; writes normalized fp32 P (final output) + scaled ctx.
// grid (SPLITK, 16, 32).
// ---------------------------------------------------------------------------
__global__ __launch_bounds__(256, 4)
void pv_norm16(const unsigned* __restrict__ p16, const unsigned* __restrict__ gv16,
               const float* __restrict__ partial, float* __restrict__ attn,
               float* __restrict__ pctx) {
    extern __shared__ unsigned pvs[];
    unsigned* Ps = pvs;                      // [PV16STG][128][20]
    unsigned* Vs = pvs + PV16_PS;            // [PV16STG][16][68]
    float* inv_s = (float*)(pvs + PV16_PS + PV16_VS);

    const int tid = threadIdx.x, lane = tid & 31, warp = tid >> 5;
    const int wm = (warp & 3) * 32, wn = (warp >> 2) * 32, kq = lane & 3;
    const int bh_i = blockIdx.z, b = bh_i >> 4, h = bh_i & 15;
    const unsigned* P16 = p16 + (size_t)bh_i * SEQ * (SEQ / 2);
    float* Pout = attn + (size_t)bh_i * SEQ * SEQ;
    const unsigned* V16 = gv16 + (size_t)b * (SEQ / 2) * DMODEL + h * DHEAD;
    float* Cc = pctx + (size_t)blockIdx.x * PS
                     + (size_t)b * SEQ * DMODEL + h * DHEAD;
    const int q0 = blockIdx.y * 128;
    const int pbase = blockIdx.x * (SEQ / SPLITK / 2);   // kpair base
    const int ntiles = (SEQ / SPLITK) / 32;              // 32 tiles of 32 keys

    auto prefetch = [&](int t) {
        int s = t % PV16STG;
        int kp0 = pbase + t * 16;
        #pragma unroll
        for (int l = 0; l < 2; l++) {
            int idx = tid + l * 256, r = idx >> 2, k4 = (idx & 3) * 4;
            cpasync16(&Ps[s*2560 + r*20 + k4], &P16[(size_t)(q0+r)*(SEQ/2) + kp0 + k4]);
        }
        {
            int kp = tid >> 4, n4 = (tid & 15) * 4;
            cpasync16(&Vs[s*1088 + kp*68 + n4], &V16[(size_t)(kp0+kp)*DMODEL + n4]);
        }
        asm volatile("cp.async.commit_group;");
    };
    #pragma unroll
    for (int t = 0; t < PV16STG - 1; t++) prefetch(t);

    if (tid < 128) {
        const float4* pp = (const float4*)&partial[((size_t)bh_i * SEQ + q0 + tid) * NKT];
        float4 p0 = pp[0], p1 = pp[1], p2 = pp[2], p3 = pp[3];
        float s = ((p0.x + p0.y) + (p0.z + p0.w)) + ((p1.x + p1.y) + (p1.z + p1.w))
                + ((p2.x + p2.y) + (p2.z + p2.w)) + ((p3.x + p3.y) + (p3.z + p3.w));
        inv_s[tid] = 1.0f / s;
    }

    float acc[2][4][4] = {};
    for (int t = 0; t < ntiles; t++) {
        int s = t % PV16STG;
        asm volatile("cp.async.wait_group %0;" :: "n"(PV16STG - 2));
        __syncthreads();
        const unsigned* Pp = &Ps[s*2560];
        const unsigned* Vp = &Vs[s*1088];
        #pragma unroll
        for (int kk = 0; kk < 16; kk += 8) {
            unsigned af[2][4];
            #pragma unroll
            for (int i = 0; i < 2; i++) {
                int m0 = wm + i * 16 + (lane >> 2);
                af[i][0] = Pp[m0*20 + kk+kq];     af[i][1] = Pp[(m0+8)*20 + kk+kq];
                af[i][2] = Pp[m0*20 + kk+kq+4];   af[i][3] = Pp[(m0+8)*20 + kk+kq+4];
            }
            #pragma unroll
            for (int j = 0; j < 4; j++) {
                int nb = wn + j * 8 + (lane >> 2);
                unsigned bf[2] = {Vp[(kk+kq)*68 + nb], Vp[(kk+kq+4)*68 + nb]};
                mma16h(acc[0][j], af[0], bf);
                mma16h(acc[1][j], af[1], bf);
            }
        }
        // write normalized fp32 P (final attention output) from the smem tile
        {
            int kcol = (pbase + t * 16) * 2;   // key column base for this tile
            #pragma unroll
            for (int l = 0; l < 2; l++) {
                int idx = tid + l * 256, r = idx >> 2, k4 = (idx & 3) * 4;
                float sc = inv_s[r];
                float4 o0, o1;
                float2 f;
                f = unpackh2(Pp[r*20 + k4 + 0]); o0.x = f.x * sc; o0.y = f.y * sc;
                f = unpackh2(Pp[r*20 + k4 + 1]); o0.z = f.x * sc; o0.w = f.y * sc;
                f = unpackh2(Pp[r*20 + k4 + 2]); o1.x = f.x * sc; o1.y = f.y * sc;
                f = unpackh2(Pp[r*20 + k4 + 3]); o1.z = f.x * sc; o1.w = f.y * sc;
                size_t base = (size_t)(q0 + r) * SEQ + kcol + k4 * 2;
                __stcs((float4*)&Pout[base],     o0);
                __stcs((float4*)&Pout[base + 4], o1);
            }
        }
        __syncthreads();
        if (t + PV16STG - 1 < ntiles) prefetch(t + PV16STG - 1);
        else asm volatile("cp.async.commit_group;");
    }
    #pragma unroll
    for (int j = 0; j < 4; j++) {
        int c = wn + j * 8 + (lane & 3) * 2;
        #pragma unroll
        for (int i = 0; i < 2; i++) {
            int rl = wm + i * 16 + (lane >> 2);
            float sc0 = inv_s[rl], sc1 = inv_s[rl + 8];
            size_t r = q0 + rl;
            float2 o0 = {acc[i][j][0] * sc0, acc[i][j][1] * sc0};
            float2 o1 = {acc[i][j][2] * sc1, acc[i][j][3] * sc1};
            *(float2*)&Cc[r * DMODEL + c]       = o0;
            *(float2*)&Cc[(r + 8) * DMODEL + c] = o1;
        }
    }
}

// ---------------------------------------------------------------------------
// Residual + LayerNorm.
// ---------------------------------------------------------------------------
__global__ void ln_kernel(const float* __restrict__ resid,
                          const float* __restrict__ x,
                          const float* __restrict__ gamma,
                          const float* __restrict__ beta,
                          float* __restrict__ out) {
    const size_t row = blockIdx.x;
    const float4* xr = reinterpret_cast<const float4*>(x + row * DMODEL);
    const float4* rr = reinterpret_cast<const float4*>(resid + row * DMODEL);
    const int t = threadIdx.x;
    __shared__ float sred[8];

    float4 a = rr[t], bv = xr[t];
    float4 v = {a.x + bv.x, a.y + bv.y, a.z + bv.z, a.w + bv.w};
    float s = v.x + v.y + v.z + v.w;
    #pragma unroll
    for (int o = 16; o > 0; o >>= 1) s += __shfl_xor_sync(0xffffffffu, s, o);
    if ((t & 31) == 0) sred[t >> 5] = s;
    __syncthreads();
    float tot = 0.f;
    #pragma unroll
    for (int i = 0; i < 8; i++) tot += sred[i];
    const float mu = tot * (1.0f / DMODEL);
    __syncthreads();

    float dx = v.x - mu, dy = v.y - mu, dz = v.z - mu, dw = v.w - mu;
    float sq = dx*dx + dy*dy + dz*dz + dw*dw;
    #pragma unroll
    for (int o = 16; o > 0; o >>= 1) sq += __shfl_xor_sync(0xffffffffu, sq, o);
    if ((t & 31) == 0) sred[t >> 5] = sq;
    __syncthreads();
    float tot2 = 0.f;
    #pragma unroll
    for (int i = 0; i < 8; i++) tot2 += sred[i];
    const float inv = rsqrtf(tot2 * (1.0f / DMODEL) + 1e-5f);

    float4 g = reinterpret_cast<const float4*>(gamma)[t];
    float4 be = reinterpret_cast<const float4*>(beta)[t];
    float4 o;
    o.x = dx * inv * g.x + be.x;
    o.y = dy * inv * g.y + be.y;
    o.z = dz * inv * g.z + be.z;
    o.w = dw * inv * g.w + be.w;
    reinterpret_cast<float4*>(out + row * DMODEL)[t] = o;
}

// ---------------------------------------------------------------------------
extern "C" void kernel_launch(void* const* d_in, const int* in_sizes, int n_in,
                              void* d_out, int out_size) {
    const float* q     = (const float*)d_in[0];
    const float* k     = (const float*)d_in[1];
    const float* v     = (const float*)d_in[2];
    const int*   mask  = (const int*)  d_in[3];
    const float* wq    = (const float*)d_in[4];
    const float* bq    = (const float*)d_in[5];
    const float* wk    = (const float*)d_in[6];
    const float* bk    = (const float*)d_in[7];
    const float* wv    = (const float*)d_in[8];
    const float* bv    = (const float*)d_in[9];
    const float* wo    = (const float*)d_in[10];
    const float* bo    = (const float*)d_in[11];
    const float* gamma = (const float*)d_in[12];
    const float* beta  = (const float*)d_in[13];

    float* out  = (float*)d_out;
    float* attn = out + ATT_OFF;

    void* sp = nullptr;
    cudaGetSymbolAddress(&sp, g_scratch);
    float* gv      = (float*)sp;
    float* go      = gv + PS;
    float* pctx    = go + PS;                 // SPLITK x PS
    float* partial = pctx + SPLITK * PS;
    unsigned* ipk  = (unsigned*)(partial + PARTIAL_SZ);   // q,k hi/lo (4*PKA)
    unsigned* wpk  = ipk + 4 * PKA;                        // wq,wk hi/lo (4*PKW)
    unsigned* opk  = wpk + 4 * PKW;                        // gq,gk hi/lo (4*PKA)
    unsigned* gv16 = opk + 4 * PKA;                        // fp16 V kpairs
    unsigned* p16  = gv16 + GV16_SZ;                       // fp16 unnorm P

    cudaFuncSetAttribute(scores_exp,   cudaFuncAttributeMaxDynamicSharedMemorySize, SC_SMEM);
    cudaFuncSetAttribute(pv_norm16,    cudaFuncAttributeMaxDynamicSharedMemorySize, PV16_SMEM);
    cudaFuncSetAttribute(gemm_nt_tf32, cudaFuncAttributeMaxDynamicSharedMemorySize, VP_SMEM);
    cudaFuncSetAttribute(gemm_o_tf32,  cudaFuncAttributeMaxDynamicSharedMemorySize, OP_SMEM);
    cudaFuncSetAttribute(gemm_qk_pk,   cudaFuncAttributeMaxDynamicSharedMemorySize, QK_SMEM);

    dim3 gPre((unsigned)((PKA / 2 + 255) / 256), 4);
    prepack_all<<<gPre, 256>>>(q, k, wq, wk, ipk, wpk);

    dim3 gQK(DMODEL / 128, MROWS / 128, 2);             // (8, 32, 2)
    gemm_qk_pk<<<gQK, 256, QK_SMEM>>>(ipk, wpk, bq, bk, opk);

    dim3 gProj(DMODEL / 128, MROWS / 128);              // (8, 32)
    gemm_nt_tf32<<<gProj, 256, VP_SMEM>>>(v, wv, bv, gv);

    pack_v16<<<(unsigned)((MROWS/2) * (DMODEL/4) / 256), 256>>>(gv, gv16);

    dim3 gScores(BATCH * NHEADS, NKT, SEQ / 128);       // (32, 16, 16)
    scores_exp<<<gScores, 256, SC_SMEM>>>(opk, mask, p16, partial);

    dim3 gPV(SPLITK, SEQ / 128, BATCH * NHEADS);        // (2, 16, 32)
    pv_norm16<<<gPV, 256, PV16_SMEM>>>(p16, gv16, partial, attn, pctx);

    gemm_o_tf32<<<gProj, 256, OP_SMEM>>>(pctx, wo, bo, go);

    ln_kernel<<<MROWS, 256>>>(q, go, gamma, beta, out);
}

// round 15
// speedup vs baseline: 1.1008x; 1.0491x over previous
#include <cuda_runtime.h>
#include <cuda_bf16.h>
#include <cuda_fp16.h>
#include <math.h>

#define BATCH 2
#define SEQ   2048
#define DMODEL 1024
#define NHEADS 16
#define DHEAD  64
#define MROWS (BATCH*SEQ)                    // 4096
#define ATT_OFF ((size_t)BATCH*SEQ*DMODEL)
#define NKT 16
#define SPLITK 2
#define OPSTG 3
#define QKSTG 4
#define VPSTG 4
#define PV16STG 3

#define PS   ((size_t)MROWS * DMODEL)        // 4M floats
#define PKA  ((size_t)MROWS * 512)           // 2M u32 kpairs
#define PKW  ((size_t)DMODEL * 512)          // 0.5M u32
#define PARTIAL_SZ ((size_t)BATCH * NHEADS * SEQ * NKT)
#define P16_SZ ((size_t)BATCH * NHEADS * SEQ * (SEQ/2))   // 64Mi u32
#define GV16_SZ ((size_t)(MROWS/2) * DMODEL)              // 2Mi u32

// go, pctx(2), partial, ipk(4*PKA), wpk(4*PKW), opk(4*PKA), gv16, p16
__device__ float g_scratch[3ull * PS + PARTIAL_SZ + 8ull * PKA + 4ull * PKW
                           + GV16_SZ + P16_SZ];

// scores smem
#define SC_SMEM (4 * 128 * 36 * 4 + 256 * 4)
// pv16 smem
#define PV16_PS (PV16STG * 128 * 20)
#define PV16_VS (PV16STG * 16 * 68)
#define PV16_SMEM ((PV16_PS + PV16_VS + 128) * 4)
// oproj smem
#define OP_AS   (OPSTG * 128 * 20)
#define OP_SMEM (3 * OP_AS * 4)
// fused proj smem: max(qk: 4 arrays x QKSTG x [128][12] u32, v: 2 x VPSTG x [128][20] f32)
#define QK_ARR  (QKSTG * 128 * 12)
#define VP_AS   (VPSTG * 128 * 20)
#define PROJ_SMEM (4 * QK_ARR * 4)          // 98304 > 81920

// ---------------------------------------------------------------------------
__device__ __forceinline__ void mma8(float* d, const unsigned* a, const unsigned* b) {
    asm volatile(
        "mma.sync.aligned.m16n8k8.row.col.f32.tf32.tf32.f32 "
        "{%0,%1,%2,%3}, {%4,%5,%6,%7}, {%8,%9}, {%0,%1,%2,%3};"
        : "+f"(d[0]), "+f"(d[1]), "+f"(d[2]), "+f"(d[3])
        : "r"(a[0]), "r"(a[1]), "r"(a[2]), "r"(a[3]), "r"(b[0]), "r"(b[1]));
}
__device__ __forceinline__ void mma16(float* d, const unsigned* a, const unsigned* b) {
    asm volatile(
        "mma.sync.aligned.m16n8k16.row.col.f32.bf16.bf16.f32 "
        "{%0,%1,%2,%3}, {%4,%5,%6,%7}, {%8,%9}, {%0,%1,%2,%3};"
        : "+f"(d[0]), "+f"(d[1]), "+f"(d[2]), "+f"(d[3])
        : "r"(a[0]), "r"(a[1]), "r"(a[2]), "r"(a[3]), "r"(b[0]), "r"(b[1]));
}
__device__ __forceinline__ void mma16h(float* d, const unsigned* a, const unsigned* b) {
    asm volatile(
        "mma.sync.aligned.m16n8k16.row.col.f32.f16.f16.f32 "
        "{%0,%1,%2,%3}, {%4,%5,%6,%7}, {%8,%9}, {%0,%1,%2,%3};"
        : "+f"(d[0]), "+f"(d[1]), "+f"(d[2]), "+f"(d[3])
        : "r"(a[0]), "r"(a[1]), "r"(a[2]), "r"(a[3]), "r"(b[0]), "r"(b[1]));
}
__device__ __forceinline__ void splitbf2(float x, float y, unsigned& hi, unsigned& lo) {
    __nv_bfloat16 hx = __float2bfloat16_rn(x);
    __nv_bfloat16 hy = __float2bfloat16_rn(y);
    __nv_bfloat16 lx = __float2bfloat16_rn(x - __bfloat162float(hx));
    __nv_bfloat16 ly = __float2bfloat16_rn(y - __bfloat162float(hy));
    hi = (unsigned)__bfloat16_as_ushort(hx) | ((unsigned)__bfloat16_as_ushort(hy) << 16);
    lo = (unsigned)__bfloat16_as_ushort(lx) | ((unsigned)__bfloat16_as_ushort(ly) << 16);
}
__device__ __forceinline__ unsigned packh2(float x, float y) {
    __half2 h = __floats2half2_rn(x, y);
    return *reinterpret_cast<unsigned*>(&h);
}
__device__ __forceinline__ float2 unpackh2(unsigned u) {
    __half2 h = *reinterpret_cast<__half2*>(&u);
    return __half22float2(h);
}
__device__ __forceinline__ void cpasync16(void* sm, const void* gm) {
    unsigned a = (unsigned)__cvta_generic_to_shared(sm);
    asm volatile("cp.async.cg.shared.global [%0], [%1], 16;" :: "r"(a), "l"(gm));
}

// ---------------------------------------------------------------------------
// Prepack q,k,wq,wk -> bf16 (hi,lo) kpair arrays.
// ---------------------------------------------------------------------------
__global__ void prepack_all(const float* __restrict__ q, const float* __restrict__ k,
                            const float* __restrict__ wq, const float* __restrict__ wk,
                            unsigned* __restrict__ ipk, unsigned* __restrict__ wpk) {
    const int z = blockIdx.y;
    const int i = blockIdx.x * 256 + threadIdx.x;
    const float* src;
    unsigned *hi, *lo;
    int half;
    if (z < 2) {
        src = z ? k : q;
        hi = ipk + (size_t)z * 2 * PKA; lo = hi + PKA;
        half = (int)(PKA / 2);
    } else {
        src = (z == 2) ? wq : wk;
        hi = wpk + (size_t)(z - 2) * 2 * PKW; lo = hi + PKW;
        half = (int)(PKW / 2);
    }
    if (i < half) {
        float4 x = ((const float4*)src)[i];
        unsigned h0, l0, h1, l1;
        splitbf2(x.x, x.y, h0, l0);
        splitbf2(x.z, x.w, h1, l1);
        ((uint2*)hi)[i] = make_uint2(h0, h1);
        ((uint2*)lo)[i] = make_uint2(l0, l1);
    }
}

// ---------------------------------------------------------------------------
// Fused projections. z=0 q, z=1 k (3xBF16 from prepacked, packed bf16 out);
// z=2 v (1xTF32 from raw fp32, fp16 kpair gv16 out). cp.async pipelined.
// grid (8, 32, 3), 256 threads, 2 CTAs/SM.
// ---------------------------------------------------------------------------
__global__ __launch_bounds__(256, 2)
void gemm_proj(const unsigned* __restrict__ apk, const unsigned* __restrict__ wpk,
               const float* __restrict__ vin, const float* __restrict__ wv,
               const float* __restrict__ bq, const float* __restrict__ bk,
               const float* __restrict__ bv, unsigned* __restrict__ outpk,
               unsigned* __restrict__ gv16) {
    extern __shared__ unsigned smu[];
    const int z = blockIdx.z;
    const int tid = threadIdx.x, lane = tid & 31, warp = tid >> 5;
    const int wm = (warp & 3) * 32, wn = (warp >> 2) * 64, kq = lane & 3;
    const int row0 = blockIdx.y * 128, col0 = blockIdx.x * 128;

    if (z < 2) {
        // ----- q/k path: 3xBF16 from prepacked operands -----
        unsigned* Ah = smu;
        unsigned* Al = smu + QK_ARR;
        unsigned* Wh = smu + 2 * QK_ARR;
        unsigned* Wl = smu + 3 * QK_ARR;
        const unsigned* Ahi = apk + (size_t)z * 2 * PKA;
        const unsigned* Alo = Ahi + PKA;
        const unsigned* Whi = wpk + (size_t)z * 2 * PKW;
        const unsigned* Wlo = Whi + PKW;
        unsigned* Ohi = outpk + (size_t)z * 2 * PKA;
        unsigned* Olo = Ohi + PKA;
        const float* bias = z ? bk : bq;
        const int ntiles = 512 / 8;

        const int pr = tid >> 1, pk4 = (tid & 1) * 4;
        auto prefetch = [&](int t) {
            int s = t & (QKSTG - 1);
            int kp0 = t * 8;
            cpasync16(&Ah[s*1536 + pr*12 + pk4], &Ahi[(size_t)(row0+pr)*512 + kp0 + pk4]);
            cpasync16(&Al[s*1536 + pr*12 + pk4], &Alo[(size_t)(row0+pr)*512 + kp0 + pk4]);
            cpasync16(&Wh[s*1536 + pr*12 + pk4], &Whi[(size_t)(col0+pr)*512 + kp0 + pk4]);
            cpasync16(&Wl[s*1536 + pr*12 + pk4], &Wlo[(size_t)(col0+pr)*512 + kp0 + pk4]);
            asm volatile("cp.async.commit_group;");
        };
        #pragma unroll
        for (int t = 0; t < QKSTG - 1; t++) prefetch(t);

        float acc[2][8][4] = {};
        for (int t = 0; t < ntiles; t++) {
            int s = t & (QKSTG - 1);
            asm volatile("cp.async.wait_group %0;" :: "n"(QKSTG - 2));
            __syncthreads();
            const unsigned* Ahp = &Ah[s*1536];
            const unsigned* Alp = &Al[s*1536];
            const unsigned* Whp = &Wh[s*1536];
            const unsigned* Wlp = &Wl[s*1536];
            unsigned ah[2][4], al[2][4];
            #pragma unroll
            for (int i = 0; i < 2; i++) {
                int m0 = wm + i * 16 + (lane >> 2);
                ah[i][0] = Ahp[m0*12 + kq];     ah[i][1] = Ahp[(m0+8)*12 + kq];
                ah[i][2] = Ahp[m0*12 + kq+4];   ah[i][3] = Ahp[(m0+8)*12 + kq+4];
                al[i][0] = Alp[m0*12 + kq];     al[i][1] = Alp[(m0+8)*12 + kq];
                al[i][2] = Alp[m0*12 + kq+4];   al[i][3] = Alp[(m0+8)*12 + kq+4];
            }
            #pragma unroll
            for (int j = 0; j < 8; j++) {
                int nb = wn + j * 8 + (lane >> 2);
                unsigned bh2[2] = {Whp[nb*12 + kq], Whp[nb*12 + kq+4]};
                unsigned bl2[2] = {Wlp[nb*12 + kq], Wlp[nb*12 + kq+4]};
                #pragma unroll
                for (int i = 0; i < 2; i++) {
                    mma16(acc[i][j], al[i], bh2);
                    mma16(acc[i][j], ah[i], bl2);
                    mma16(acc[i][j], ah[i], bh2);
                }
            }
            __syncthreads();
            if (t + QKSTG - 1 < ntiles) prefetch(t + QKSTG - 1);
            else asm volatile("cp.async.commit_group;");
        }
        #pragma unroll
        for (int j = 0; j < 8; j++) {
            int c = col0 + wn + j * 8 + (lane & 3) * 2;
            float2 bb = *(const float2*)&bias[c];
            #pragma unroll
            for (int i = 0; i < 2; i++) {
                size_t r = row0 + wm + i * 16 + (lane >> 2);
                unsigned h, l;
                splitbf2(acc[i][j][0] + bb.x, acc[i][j][1] + bb.y, h, l);
                Ohi[r * 512 + (c >> 1)] = h;  Olo[r * 512 + (c >> 1)] = l;
                splitbf2(acc[i][j][2] + bb.x, acc[i][j][3] + bb.y, h, l);
                Ohi[(r + 8) * 512 + (c >> 1)] = h;  Olo[(r + 8) * 512 + (c >> 1)] = l;
            }
        }
    } else {
        // ----- v path: 1xTF32 from raw fp32; fp16 kpair epilogue -----
        float* As2 = (float*)smu;            // [VPSTG][128][20]
        float* Ws2 = As2 + VP_AS;
        const int ntiles = DMODEL / 16;

        auto prefetch = [&](int t) {
            int s = t & (VPSTG - 1);
            int k0 = t * 16;
            #pragma unroll
            for (int l = 0; l < 2; l++) {
                int c = tid + l * 256, r = c >> 2, qd = (c & 3) * 4;
                cpasync16(&As2[s*2560 + r*20 + qd], &vin[(size_t)(row0+r)*DMODEL + k0 + qd]);
                cpasync16(&Ws2[s*2560 + r*20 + qd], &wv[(size_t)(col0+r)*DMODEL + k0 + qd]);
            }
            asm volatile("cp.async.commit_group;");
        };
        #pragma unroll
        for (int t = 0; t < VPSTG - 1; t++) prefetch(t);

        float acc[2][8][4] = {};
        for (int t = 0; t < ntiles; t++) {
            int s = t & (VPSTG - 1);
            asm volatile("cp.async.wait_group %0;" :: "n"(VPSTG - 2));
            __syncthreads();
            const float* Ap = &As2[s*2560];
            const float* Wp = &Ws2[s*2560];
            #pragma unroll
            for (int kk = 0; kk < 16; kk += 8) {
                const int kr = kk + (lane & 3), m0 = wm + (lane >> 2);
                unsigned af[2][4];
                #pragma unroll
                for (int i = 0; i < 2; i++) {
                    af[i][0] = __float_as_uint(Ap[(m0+i*16)*20 + kr]);
                    af[i][1] = __float_as_uint(Ap[(m0+i*16+8)*20 + kr]);
                    af[i][2] = __float_as_uint(Ap[(m0+i*16)*20 + kr+4]);
                    af[i][3] = __float_as_uint(Ap[(m0+i*16+8)*20 + kr+4]);
                }
                #pragma unroll
                for (int j = 0; j < 8; j++) {
                    int nb = wn + j * 8 + (lane >> 2);
                    unsigned bf[2] = {__float_as_uint(Wp[nb*20 + kr]),
                                      __float_as_uint(Wp[nb*20 + kr+4])};
                    mma8(acc[0][j], af[0], bf);
                    mma8(acc[1][j], af[1], bf);
                }
            }
            __syncthreads();
            if (t + VPSTG - 1 < ntiles) prefetch(t + VPSTG - 1);
            else asm volatile("cp.async.commit_group;");
        }
        // Epilogue: add bias, pair rows (r, r+1) via shfl, write fp16 kpairs.
        const int rg = lane >> 2;
        const bool evenrow = (rg & 1) == 0;
        #pragma unroll
        for (int j = 0; j < 8; j++) {
            int c = col0 + wn + j * 8 + (lane & 3) * 2;
            float2 bb = *(const float2*)&bv[c];
            #pragma unroll
            for (int i = 0; i < 2; i++) {
                float x0 = acc[i][j][0] + bb.x, y0 = acc[i][j][1] + bb.y;   // row r
                float x1 = acc[i][j][2] + bb.x, y1 = acc[i][j][3] + bb.y;   // row r+8
                float px0 = __shfl_down_sync(0xffffffffu, x0, 4);
                float py0 = __shfl_down_sync(0xffffffffu, y0, 4);
                float px1 = __shfl_down_sync(0xffffffffu, x1, 4);
                float py1 = __shfl_down_sync(0xffffffffu, y1, 4);
                if (evenrow) {
                    int r = row0 + wm + i * 16 + rg;          // even
                    size_t t0 = (size_t)(r >> 1);
                    size_t t1 = (size_t)((r + 8) >> 1);
                    uint2 o0 = make_uint2(packh2(x0, px0), packh2(y0, py0));
                    uint2 o1 = make_uint2(packh2(x1, px1), packh2(y1, py1));
                    *(uint2*)&gv16[t0 * DMODEL + c] = o0;
                    *(uint2*)&gv16[t1 * DMODEL + c] = o1;
                }
            }
        }
    }
}

// ---------------------------------------------------------------------------
// O projection: A = pctx0 + pctx1, cp.async 3-stage, 3 streams.
// ---------------------------------------------------------------------------
__global__ __launch_bounds__(256, 2)
void gemm_o_tf32(const float* __restrict__ pctx, const float* __restrict__ W,
                 const float* __restrict__ bias, float* __restrict__ C) {
    extern __shared__ float osm[];
    float* As0 = osm;
    float* As1 = osm + OP_AS;
    float* Ws2 = osm + 2 * OP_AS;
    const int tid = threadIdx.x, lane = tid & 31, warp = tid >> 5;
    const int wm = (warp & 3) * 32, wn = (warp >> 2) * 64;
    const int row0 = blockIdx.y * 128, col0 = blockIdx.x * 128;
    const int ntiles = DMODEL / 16;

    auto prefetch = [&](int t) {
        int s = t % OPSTG;
        int k0 = t * 16;
        #pragma unroll
        for (int l = 0; l < 2; l++) {
            int c = tid + l * 256, r = c >> 2, qd = (c & 3) * 4;
            size_t offA = (size_t)(row0 + r) * DMODEL + k0 + qd;
            cpasync16(&As0[s*2560 + r*20 + qd], &pctx[offA]);
            cpasync16(&As1[s*2560 + r*20 + qd], &pctx[offA + PS]);
            cpasync16(&Ws2[s*2560 + r*20 + qd], &W[(size_t)(col0+r)*DMODEL + k0 + qd]);
        }
        asm volatile("cp.async.commit_group;");
    };
    #pragma unroll
    for (int t = 0; t < OPSTG - 1; t++) prefetch(t);

    float acc[2][8][4] = {};
    for (int t = 0; t < ntiles; t++) {
        int s = t % OPSTG;
        asm volatile("cp.async.wait_group %0;" :: "n"(OPSTG - 2));
        __syncthreads();
        const float* A0 = &As0[s*2560];
        const float* A1 = &As1[s*2560];
        const float* Wp = &Ws2[s*2560];
        #pragma unroll
        for (int kk = 0; kk < 16; kk += 8) {
            const int kr = kk + (lane & 3), m0 = wm + (lane >> 2);
            unsigned af[2][4];
            #pragma unroll
            for (int i = 0; i < 2; i++) {
                int r0 = (m0 + i*16) * 20, r1 = (m0 + i*16 + 8) * 20;
                af[i][0] = __float_as_uint(A0[r0 + kr]   + A1[r0 + kr]);
                af[i][1] = __float_as_uint(A0[r1 + kr]   + A1[r1 + kr]);
                af[i][2] = __float_as_uint(A0[r0 + kr+4] + A1[r0 + kr+4]);
                af[i][3] = __float_as_uint(A0[r1 + kr+4] + A1[r1 + kr+4]);
            }
            #pragma unroll
            for (int j = 0; j < 8; j++) {
                int nb = wn + j * 8 + (lane >> 2);
                unsigned bf[2] = {__float_as_uint(Wp[nb*20 + kr]),
                                  __float_as_uint(Wp[nb*20 + kr+4])};
                mma8(acc[0][j], af[0], bf);
                mma8(acc[1][j], af[1], bf);
            }
        }
        __syncthreads();
        if (t + OPSTG - 1 < ntiles) prefetch(t + OPSTG - 1);
        else asm volatile("cp.async.commit_group;");
    }
    #pragma unroll
    for (int j = 0; j < 8; j++) {
        int c = col0 + wn + j * 8 + (lane & 3) * 2;
        float2 bb = *(const float2*)&bias[c];
        #pragma unroll
        for (int i = 0; i < 2; i++) {
            size_t r = row0 + wm + i * 16 + (lane >> 2);
            float2 o0 = {acc[i][j][0] + bb.x, acc[i][j][1] + bb.y};
            float2 o1 = {acc[i][j][2] + bb.x, acc[i][j][3] + bb.y};
            *(float2*)&C[r * DMODEL + c]       = o0;
            *(float2*)&C[(r + 8) * DMODEL + c] = o1;
        }
    }
}

// ---------------------------------------------------------------------------
// Fused scores (3xBF16) from PREPACKED gq/gk + mask + exp -> fp16 unnorm P
// + fp32 rowsum partials. grid (32 bh, NKT ktile, 16 qtile).
// ---------------------------------------------------------------------------
__global__ __launch_bounds__(256, 2)
void scores_exp(const unsigned* __restrict__ opk, const int* __restrict__ mask,
                unsigned* __restrict__ p16, float* __restrict__ partial) {
    extern __shared__ unsigned dsm[];
    unsigned* Qh = dsm;                    // [128][36]
    unsigned* Ql = Qh + 128*36;
    unsigned* Kh = Ql + 128*36;
    unsigned* Kl = Kh + 128*36;
    float* sums = (float*)(Kl + 128*36);

    const int tid = threadIdx.x, lane = tid & 31, warp = tid >> 5;
    const int wm = (warp & 3) * 32, wn = (warp >> 2) * 64, kq = lane & 3;
    const int bh_i = blockIdx.x, b = bh_i >> 4, h = bh_i & 15;
    const int c0 = blockIdx.y * 128, q0 = blockIdx.z * 128;
    const unsigned* Qhi = opk;
    const unsigned* Qlo = opk + PKA;
    const unsigned* Khi = opk + 2 * PKA;
    const unsigned* Klo = opk + 3 * PKA;
    const int hoff = h * 32;

    #pragma unroll
    for (int l = 0; l < 4; l++) {
        int idx = tid + l * 256, r = idx >> 3, kp4 = (idx & 7) * 4;
        size_t qoff = (size_t)(b * SEQ + q0 + r) * 512 + hoff + kp4;
        size_t koff = (size_t)(b * SEQ + c0 + r) * 512 + hoff + kp4;
        cpasync16(&Qh[r*36 + kp4], &Qhi[qoff]);
        cpasync16(&Ql[r*36 + kp4], &Qlo[qoff]);
        cpasync16(&Kh[r*36 + kp4], &Khi[koff]);
        cpasync16(&Kl[r*36 + kp4], &Klo[koff]);
    }
    asm volatile("cp.async.commit_group;");
    asm volatile("cp.async.wait_group 0;");
    __syncthreads();

    float acc[2][8][4] = {};
    #pragma unroll
    for (int kk = 0; kk < 32; kk += 8) {
        unsigned ah[2][4], al[2][4];
        #pragma unroll
        for (int i = 0; i < 2; i++) {
            int m0 = wm + i * 16 + (lane >> 2);
            ah[i][0] = Qh[m0*36 + kk+kq];     ah[i][1] = Qh[(m0+8)*36 + kk+kq];
            ah[i][2] = Qh[m0*36 + kk+kq+4];   ah[i][3] = Qh[(m0+8)*36 + kk+kq+4];
            al[i][0] = Ql[m0*36 + kk+kq];     al[i][1] = Ql[(m0+8)*36 + kk+kq];
            al[i][2] = Ql[m0*36 + kk+kq+4];   al[i][3] = Ql[(m0+8)*36 + kk+kq+4];
        }
        #pragma unroll
        for (int j = 0; j < 8; j++) {
            int nb = wn + j * 8 + (lane >> 2);
            unsigned bh2[2] = {Kh[nb*36 + kk+kq], Kh[nb*36 + kk+kq+4]};
            unsigned bl2[2] = {Kl[nb*36 + kk+kq], Kl[nb*36 + kk+kq+4]};
            #pragma unroll
            for (int i = 0; i < 2; i++) {
                mma16(acc[i][j], al[i], bh2);
                mma16(acc[i][j], ah[i], bl2);
                mma16(acc[i][j], ah[i], bh2);
            }
        }
    }

    const int* mrow = mask + (size_t)b * SEQ * SEQ;
    unsigned* out16 = p16 + (size_t)bh_i * SEQ * (SEQ / 2);
    float rs[2][2] = {};
    #pragma unroll
    for (int j = 0; j < 8; j++) {
        int c = c0 + wn + j * 8 + (lane & 3) * 2;
        int kp = c >> 1;
        #pragma unroll
        for (int i = 0; i < 2; i++) {
            size_t r = q0 + wm + i * 16 + (lane >> 2);
            int2 m0v = *(const int2*)&mrow[r * SEQ + c];
            int2 m1v = *(const int2*)&mrow[(r + 8) * SEQ + c];
            float2 o0, o1;
            o0.x = m0v.x ? __expf(acc[i][j][0] * 0.125f) : 0.f;
            o0.y = m0v.y ? __expf(acc[i][j][1] * 0.125f) : 0.f;
            o1.x = m1v.x ? __expf(acc[i][j][2] * 0.125f) : 0.f;
            o1.y = m1v.y ? __expf(acc[i][j][3] * 0.125f) : 0.f;
            out16[r * (SEQ/2) + kp]       = packh2(o0.x, o0.y);
            out16[(r + 8) * (SEQ/2) + kp] = packh2(o1.x, o1.y);
            rs[i][0] += o0.x + o0.y;
            rs[i][1] += o1.x + o1.y;
        }
    }
    #pragma unroll
    for (int i = 0; i < 2; i++)
        #pragma unroll
        for (int hh = 0; hh < 2; hh++) {
            float v = rs[i][hh];
            v += __shfl_xor_sync(0xffffffffu, v, 1);
            v += __shfl_xor_sync(0xffffffffu, v, 2);
            if ((lane & 3) == 0)
                sums[(warp >> 2) * 128 + wm + i * 16 + hh * 8 + (lane >> 2)] = v;
        }
    __syncthreads();
    if (tid < 128) {
        float tot = sums[tid] + sums[128 + tid];
        partial[((size_t)bh_i * SEQ + q0 + tid) * NKT + blockIdx.y] = tot;
    }
}

// ---------------------------------------------------------------------------
// Fused PV (f16 mma, split-K=2), cp.async 3-stage.
// ---------------------------------------------------------------------------
__global__ __launch_bounds__(256, 4)
void pv_norm16(const unsigned* __restrict__ p16, const unsigned* __restrict__ gv16,
               const float* __restrict__ partial, float* __restrict__ attn,
               float* __restrict__ pctx) {
    extern __shared__ unsigned pvs[];
    unsigned* Ps = pvs;                      // [PV16STG][128][20]
    unsigned* Vs = pvs + PV16_PS;            // [PV16STG][16][68]
    float* inv_s = (float*)(pvs + PV16_PS + PV16_VS);

    const int tid = threadIdx.x, lane = tid & 31, warp = tid >> 5;
    const int wm = (warp & 3) * 32, wn = (warp >> 2) * 32, kq = lane & 3;
    const int bh_i = blockIdx.z, b = bh_i >> 4, h = bh_i & 15;
    const unsigned* P16 = p16 + (size_t)bh_i * SEQ * (SEQ / 2);
    float* Pout = attn + (size_t)bh_i * SEQ * SEQ;
    const unsigned* V16 = gv16 + (size_t)b * (SEQ / 2) * DMODEL + h * DHEAD;
    float* Cc = pctx + (size_t)blockIdx.x * PS
                     + (size_t)b * SEQ * DMODEL + h * DHEAD;
    const int q0 = blockIdx.y * 128;
    const int pbase = blockIdx.x * (SEQ / SPLITK / 2);
    const int ntiles = (SEQ / SPLITK) / 32;

    auto prefetch = [&](int t) {
        int s = t % PV16STG;
        int kp0 = pbase + t * 16;
        #pragma unroll
        for (int l = 0; l < 2; l++) {
            int idx = tid + l * 256, r = idx >> 2, k4 = (idx & 3) * 4;
            cpasync16(&Ps[s*2560 + r*20 + k4], &P16[(size_t)(q0+r)*(SEQ/2) + kp0 + k4]);
        }
        {
            int kp = tid >> 4, n4 = (tid & 15) * 4;
            cpasync16(&Vs[s*1088 + kp*68 + n4], &V16[(size_t)(kp0+kp)*DMODEL + n4]);
        }
        asm volatile("cp.async.commit_group;");
    };
    #pragma unroll
    for (int t = 0; t < PV16STG - 1; t++) prefetch(t);

    if (tid < 128) {
        const float4* pp = (const float4*)&partial[((size_t)bh_i * SEQ + q0 + tid) * NKT];
        float4 p0 = pp[0], p1 = pp[1], p2 = pp[2], p3 = pp[3];
        float s = ((p0.x + p0.y) + (p0.z + p0.w)) + ((p1.x + p1.y) + (p1.z + p1.w))
                + ((p2.x + p2.y) + (p2.z + p2.w)) + ((p3.x + p3.y) + (p3.z + p3.w));
        inv_s[tid] = 1.0f / s;
    }

    float acc[2][4][4] = {};
    for (int t = 0; t < ntiles; t++) {
        int s = t % PV16STG;
        asm volatile("cp.async.wait_group %0;" :: "n"(PV16STG - 2));
        __syncthreads();
        const unsigned* Pp = &Ps[s*2560];
        const unsigned* Vp = &Vs[s*1088];
        #pragma unroll
        for (int kk = 0; kk < 16; kk += 8) {
            unsigned af[2][4];
            #pragma unroll
            for (int i = 0; i < 2; i++) {
                int m0 = wm + i * 16 + (lane >> 2);
                af[i][0] = Pp[m0*20 + kk+kq];     af[i][1] = Pp[(m0+8)*20 + kk+kq];
                af[i][2] = Pp[m0*20 + kk+kq+4];   af[i][3] = Pp[(m0+8)*20 + kk+kq+4];
            }
            #pragma unroll
            for (int j = 0; j < 4; j++) {
                int nb = wn + j * 8 + (lane >> 2);
                unsigned bf[2] = {Vp[(kk+kq)*68 + nb], Vp[(kk+kq+4)*68 + nb]};
                mma16h(acc[0][j], af[0], bf);
                mma16h(acc[1][j], af[1], bf);
            }
        }
        {
            int kcol = (pbase + t * 16) * 2;
            #pragma unroll
            for (int l = 0; l < 2; l++) {
                int idx = tid + l * 256, r = idx >> 2, k4 = (idx & 3) * 4;
                float sc = inv_s[r];
                float4 o0, o1;
                float2 f;
                f = unpackh2(Pp[r*20 + k4 + 0]); o0.x = f.x * sc; o0.y = f.y * sc;
                f = unpackh2(Pp[r*20 + k4 + 1]); o0.z = f.x * sc; o0.w = f.y * sc;
                f = unpackh2(Pp[r*20 + k4 + 2]); o1.x = f.x * sc; o1.y = f.y * sc;
                f = unpackh2(Pp[r*20 + k4 + 3]); o1.z = f.x * sc; o1.w = f.y * sc;
                size_t base = (size_t)(q0 + r) * SEQ + kcol + k4 * 2;
                __stcs((float4*)&Pout[base],     o0);
                __stcs((float4*)&Pout[base + 4], o1);
            }
        }
        __syncthreads();
        if (t + PV16STG - 1 < ntiles) prefetch(t + PV16STG - 1);
        else asm volatile("cp.async.commit_group;");
    }
    #pragma unroll
    for (int j = 0; j < 4; j++) {
        int c = wn + j * 8 + (lane & 3) * 2;
        #pragma unroll
        for (int i = 0; i < 2; i++) {
            int rl = wm + i * 16 + (lane >> 2);
            float sc0 = inv_s[rl], sc1 = inv_s[rl + 8];
            size_t r = q0 + rl;
            float2 o0 = {acc[i][j][0] * sc0, acc[i][j][1] * sc0};
            float2 o1 = {acc[i][j][2] * sc1, acc[i][j][3] * sc1};
            *(float2*)&Cc[r * DMODEL + c]       = o0;
            *(float2*)&Cc[(r + 8) * DMODEL + c] = o1;
        }
    }
}

// ---------------------------------------------------------------------------
// Residual + LayerNorm.
// ---------------------------------------------------------------------------
__global__ void ln_kernel(const float* __restrict__ resid,
                          const float* __restrict__ x,
                          const float* __restrict__ gamma,
                          const float* __restrict__ beta,
                          float* __restrict__ out) {
    const size_t row = blockIdx.x;
    const float4* xr = reinterpret_cast<const float4*>(x + row * DMODEL);
    const float4* rr = reinterpret_cast<const float4*>(resid + row * DMODEL);
    const int t = threadIdx.x;
    __shared__ float sred[8];

    float4 a = rr[t], bv = xr[t];
    float4 v = {a.x + bv.x, a.y + bv.y, a.z + bv.z, a.w + bv.w};
    float s = v.x + v.y + v.z + v.w;
    #pragma unroll
    for (int o = 16; o > 0; o >>= 1) s += __shfl_xor_sync(0xffffffffu, s, o);
    if ((t & 31) == 0) sred[t >> 5] = s;
    __syncthreads();
    float tot = 0.f;
    #pragma unroll
    for (int i = 0; i < 8; i++) tot += sred[i];
    const float mu = tot * (1.0f / DMODEL);
    __syncthreads();

    float dx = v.x - mu, dy = v.y - mu, dz = v.z - mu, dw = v.w - mu;
    float sq = dx*dx + dy*dy + dz*dz + dw*dw;
    #pragma unroll
    for (int o = 16; o > 0; o >>= 1) sq += __shfl_xor_sync(0xffffffffu, sq, o);
    if ((t & 31) == 0) sred[t >> 5] = sq;
    __syncthreads();
    float tot2 = 0.f;
    #pragma unroll
    for (int i = 0; i < 8; i++) tot2 += sred[i];
    const float inv = rsqrtf(tot2 * (1.0f / DMODEL) + 1e-5f);

    float4 g = reinterpret_cast<const float4*>(gamma)[t];
    float4 be = reinterpret_cast<const float4*>(beta)[t];
    float4 o;
    o.x = dx * inv * g.x + be.x;
    o.y = dy * inv * g.y + be.y;
    o.z = dz * inv * g.z + be.z;
    o.w = dw * inv * g.w + be.w;
    reinterpret_cast<float4*>(out + row * DMODEL)[t] = o;
}

// ---------------------------------------------------------------------------
extern "C" void kernel_launch(void* const* d_in, const int* in_sizes, int n_in,
                              void* d_out, int out_size) {
    const float* q     = (const float*)d_in[0];
    const float* k     = (const float*)d_in[1];
    const float* v     = (const float*)d_in[2];
    const int*   mask  = (const int*)  d_in[3];
    const float* wq    = (const float*)d_in[4];
    const float* bq    = (const float*)d_in[5];
    const float* wk    = (const float*)d_in[6];
    const float* bk    = (const float*)d_in[7];
    const float* wv    = (const float*)d_in[8];
    const float* bv    = (const float*)d_in[9];
    const float* wo    = (const float*)d_in[10];
    const float* bo    = (const float*)d_in[11];
    const float* gamma = (const float*)d_in[12];
    const float* beta  = (const float*)d_in[13];

    float* out  = (float*)d_out;
    float* attn = out + ATT_OFF;

    void* sp = nullptr;
    cudaGetSymbolAddress(&sp, g_scratch);
    float* go      = (float*)sp;
    float* pctx    = go + PS;                 // SPLITK x PS
    float* partial = pctx + SPLITK * PS;
    unsigned* ipk  = (unsigned*)(partial + PARTIAL_SZ);   // q,k hi/lo (4*PKA)
    unsigned* wpk  = ipk + 4 * PKA;                        // wq,wk hi/lo (4*PKW)
    unsigned* opk  = wpk + 4 * PKW;                        // gq,gk hi/lo (4*PKA)
    unsigned* gv16 = opk + 4 * PKA;                        // fp16 V kpairs
    unsigned* p16  = gv16 + GV16_SZ;                       // fp16 unnorm P

    cudaFuncSetAttribute(scores_exp,  cudaFuncAttributeMaxDynamicSharedMemorySize, SC_SMEM);
    cudaFuncSetAttribute(pv_norm16,   cudaFuncAttributeMaxDynamicSharedMemorySize, PV16_SMEM);
    cudaFuncSetAttribute(gemm_o_tf32, cudaFuncAttributeMaxDynamicSharedMemorySize, OP_SMEM);
    cudaFuncSetAttribute(gemm_proj,   cudaFuncAttributeMaxDynamicSharedMemorySize, PROJ_SMEM);

    dim3 gPre((unsigned)((PKA / 2 + 255) / 256), 4);
    prepack_all<<<gPre, 256>>>(q, k, wq, wk, ipk, wpk);

    dim3 gProj3(DMODEL / 128, MROWS / 128, 3);          // (8, 32, 3): q, k, v
    gemm_proj<<<gProj3, 256, PROJ_SMEM>>>(ipk, wpk, v, wv, bq, bk, bv, opk, gv16);

    dim3 gScores(BATCH * NHEADS, NKT, SEQ / 128);       // (32, 16, 16)
    scores_exp<<<gScores, 256, SC_SMEM>>>(opk, mask, p16, partial);

    dim3 gPV(SPLITK, SEQ / 128, BATCH * NHEADS);        // (2, 16, 32)
    pv_norm16<<<gPV, 256, PV16_SMEM>>>(p16, gv16, partial, attn, pctx);

    dim3 gProj(DMODEL / 128, MROWS / 128);              // (8, 32)
    gemm_o_tf32<<<gProj, 256, OP_SMEM>>>(pctx, wo, bo, go);

    ln_kernel<<<MROWS, 256>>>(q, go, gamma, beta, out);
}

// round 16
// speedup vs baseline: 1.1042x; 1.0030x over previous
#include <cuda_runtime.h>
#include <cuda_bf16.h>
#include <cuda_fp16.h>
#include <math.h>

#define BATCH 2
#define SEQ   2048
#define DMODEL 1024
#define NHEADS 16
#define DHEAD  64
#define MROWS (BATCH*SEQ)                    // 4096
#define ATT_OFF ((size_t)BATCH*SEQ*DMODEL)
#define NKT 16
#define OPSTG 4
#define QKSTG 4
#define VPSTG 4
#define PV16STG 3

#define PS   ((size_t)MROWS * DMODEL)        // 4M floats
#define PKA  ((size_t)MROWS * 512)           // 2M u32 kpairs
#define PKW  ((size_t)DMODEL * 512)          // 0.5M u32
#define PARTIAL_SZ ((size_t)BATCH * NHEADS * SEQ * NKT)
#define P16_SZ ((size_t)BATCH * NHEADS * SEQ * (SEQ/2))   // 64Mi u32
#define GV16_SZ ((size_t)(MROWS/2) * DMODEL)              // 2Mi u32
#define M8_W   ((size_t)BATCH * SEQ * SEQ / 4)            // mask8 in u32 words

// go, pctx, partial, ipk(4*PKA), wpk(4*PKW), opk(4*PKA), gv16, p16, mask8
__device__ float g_scratch[2ull * PS + PARTIAL_SZ + 8ull * PKA + 4ull * PKW
                           + GV16_SZ + P16_SZ + M8_W];

// scores smem
#define SC_SMEM (4 * 128 * 36 * 4 + 256 * 4)
// pv16 smem
#define PV16_PS (PV16STG * 128 * 20)
#define PV16_VS (PV16STG * 16 * 68)
#define PV16_SMEM ((PV16_PS + PV16_VS + 128) * 4)
// oproj smem: 2 streams x OPSTG x [128][20]
#define OP_AS   (OPSTG * 128 * 20)
#define OP_SMEM (2 * OP_AS * 4)
// fused proj smem
#define QK_ARR  (QKSTG * 128 * 12)
#define VP_AS   (VPSTG * 128 * 20)
#define PROJ_SMEM (4 * QK_ARR * 4)

// ---------------------------------------------------------------------------
__device__ __forceinline__ void mma8(float* d, const unsigned* a, const unsigned* b) {
    asm volatile(
        "mma.sync.aligned.m16n8k8.row.col.f32.tf32.tf32.f32 "
        "{%0,%1,%2,%3}, {%4,%5,%6,%7}, {%8,%9}, {%0,%1,%2,%3};"
        : "+f"(d[0]), "+f"(d[1]), "+f"(d[2]), "+f"(d[3])
        : "r"(a[0]), "r"(a[1]), "r"(a[2]), "r"(a[3]), "r"(b[0]), "r"(b[1]));
}
__device__ __forceinline__ void mma16(float* d, const unsigned* a, const unsigned* b) {
    asm volatile(
        "mma.sync.aligned.m16n8k16.row.col.f32.bf16.bf16.f32 "
        "{%0,%1,%2,%3}, {%4,%5,%6,%7}, {%8,%9}, {%0,%1,%2,%3};"
        : "+f"(d[0]), "+f"(d[1]), "+f"(d[2]), "+f"(d[3])
        : "r"(a[0]), "r"(a[1]), "r"(a[2]), "r"(a[3]), "r"(b[0]), "r"(b[1]));
}
__device__ __forceinline__ void mma16h(float* d, const unsigned* a, const unsigned* b) {
    asm volatile(
        "mma.sync.aligned.m16n8k16.row.col.f32.f16.f16.f32 "
        "{%0,%1,%2,%3}, {%4,%5,%6,%7}, {%8,%9}, {%0,%1,%2,%3};"
        : "+f"(d[0]), "+f"(d[1]), "+f"(d[2]), "+f"(d[3])
        : "r"(a[0]), "r"(a[1]), "r"(a[2]), "r"(a[3]), "r"(b[0]), "r"(b[1]));
}
__device__ __forceinline__ void splitbf2(float x, float y, unsigned& hi, unsigned& lo) {
    __nv_bfloat16 hx = __float2bfloat16_rn(x);
    __nv_bfloat16 hy = __float2bfloat16_rn(y);
    __nv_bfloat16 lx = __float2bfloat16_rn(x - __bfloat162float(hx));
    __nv_bfloat16 ly = __float2bfloat16_rn(y - __bfloat162float(hy));
    hi = (unsigned)__bfloat16_as_ushort(hx) | ((unsigned)__bfloat16_as_ushort(hy) << 16);
    lo = (unsigned)__bfloat16_as_ushort(lx) | ((unsigned)__bfloat16_as_ushort(ly) << 16);
}
__device__ __forceinline__ unsigned packh2(float x, float y) {
    __half2 h = __floats2half2_rn(x, y);
    return *reinterpret_cast<unsigned*>(&h);
}
__device__ __forceinline__ float2 unpackh2(unsigned u) {
    __half2 h = *reinterpret_cast<__half2*>(&u);
    return __half22float2(h);
}
__device__ __forceinline__ void cpasync16(void* sm, const void* gm) {
    unsigned a = (unsigned)__cvta_generic_to_shared(sm);
    asm volatile("cp.async.cg.shared.global [%0], [%1], 16;" :: "r"(a), "l"(gm));
}

// ---------------------------------------------------------------------------
// Prepack q,k,wq,wk -> bf16 (hi,lo) kpair arrays.
// ---------------------------------------------------------------------------
__global__ void prepack_all(const float* __restrict__ q, const float* __restrict__ k,
                            const float* __restrict__ wq, const float* __restrict__ wk,
                            unsigned* __restrict__ ipk, unsigned* __restrict__ wpk) {
    const int z = blockIdx.y;
    const int i = blockIdx.x * 256 + threadIdx.x;
    const float* src;
    unsigned *hi, *lo;
    int half;
    if (z < 2) {
        src = z ? k : q;
        hi = ipk + (size_t)z * 2 * PKA; lo = hi + PKA;
        half = (int)(PKA / 2);
    } else {
        src = (z == 2) ? wq : wk;
        hi = wpk + (size_t)(z - 2) * 2 * PKW; lo = hi + PKW;
        half = (int)(PKW / 2);
    }
    if (i < half) {
        float4 x = ((const float4*)src)[i];
        unsigned h0, l0, h1, l1;
        splitbf2(x.x, x.y, h0, l0);
        splitbf2(x.z, x.w, h1, l1);
        ((uint2*)hi)[i] = make_uint2(h0, h1);
        ((uint2*)lo)[i] = make_uint2(l0, l1);
    }
}

// ---------------------------------------------------------------------------
// Prepack mask int32 -> uint8.
// ---------------------------------------------------------------------------
__global__ void prepack_mask(const int* __restrict__ m, unsigned char* __restrict__ m8) {
    size_t i = (size_t)blockIdx.x * 256 + threadIdx.x;    // over M8_W
    int4 v = ((const int4*)m)[i];
    uchar4 o;
    o.x = (unsigned char)v.x; o.y = (unsigned char)v.y;
    o.z = (unsigned char)v.z; o.w = (unsigned char)v.w;
    ((uchar4*)m8)[i] = o;
}

// ---------------------------------------------------------------------------
// Fused projections. z=0 q, z=1 k (3xBF16, packed bf16 out);
// z=2 v (1xTF32, fp16 kpair gv16 out). cp.async pipelined.
// ---------------------------------------------------------------------------
__global__ __launch_bounds__(256, 2)
void gemm_proj(const unsigned* __restrict__ apk, const unsigned* __restrict__ wpk,
               const float* __restrict__ vin, const float* __restrict__ wv,
               const float* __restrict__ bq, const float* __restrict__ bk,
               const float* __restrict__ bv, unsigned* __restrict__ outpk,
               unsigned* __restrict__ gv16) {
    extern __shared__ unsigned smu[];
    const int z = blockIdx.z;
    const int tid = threadIdx.x, lane = tid & 31, warp = tid >> 5;
    const int wm = (warp & 3) * 32, wn = (warp >> 2) * 64, kq = lane & 3;
    const int row0 = blockIdx.y * 128, col0 = blockIdx.x * 128;

    if (z < 2) {
        unsigned* Ah = smu;
        unsigned* Al = smu + QK_ARR;
        unsigned* Wh = smu + 2 * QK_ARR;
        unsigned* Wl = smu + 3 * QK_ARR;
        const unsigned* Ahi = apk + (size_t)z * 2 * PKA;
        const unsigned* Alo = Ahi + PKA;
        const unsigned* Whi = wpk + (size_t)z * 2 * PKW;
        const unsigned* Wlo = Whi + PKW;
        unsigned* Ohi = outpk + (size_t)z * 2 * PKA;
        unsigned* Olo = Ohi + PKA;
        const float* bias = z ? bk : bq;
        const int ntiles = 512 / 8;

        const int pr = tid >> 1, pk4 = (tid & 1) * 4;
        auto prefetch = [&](int t) {
            int s = t & (QKSTG - 1);
            int kp0 = t * 8;
            cpasync16(&Ah[s*1536 + pr*12 + pk4], &Ahi[(size_t)(row0+pr)*512 + kp0 + pk4]);
            cpasync16(&Al[s*1536 + pr*12 + pk4], &Alo[(size_t)(row0+pr)*512 + kp0 + pk4]);
            cpasync16(&Wh[s*1536 + pr*12 + pk4], &Whi[(size_t)(col0+pr)*512 + kp0 + pk4]);
            cpasync16(&Wl[s*1536 + pr*12 + pk4], &Wlo[(size_t)(col0+pr)*512 + kp0 + pk4]);
            asm volatile("cp.async.commit_group;");
        };
        #pragma unroll
        for (int t = 0; t < QKSTG - 1; t++) prefetch(t);

        float acc[2][8][4] = {};
        for (int t = 0; t < ntiles; t++) {
            int s = t & (QKSTG - 1);
            asm volatile("cp.async.wait_group %0;" :: "n"(QKSTG - 2));
            __syncthreads();
            const unsigned* Ahp = &Ah[s*1536];
            const unsigned* Alp = &Al[s*1536];
            const unsigned* Whp = &Wh[s*1536];
            const unsigned* Wlp = &Wl[s*1536];
            unsigned ah[2][4], al[2][4];
            #pragma unroll
            for (int i = 0; i < 2; i++) {
                int m0 = wm + i * 16 + (lane >> 2);
                ah[i][0] = Ahp[m0*12 + kq];     ah[i][1] = Ahp[(m0+8)*12 + kq];
                ah[i][2] = Ahp[m0*12 + kq+4];   ah[i][3] = Ahp[(m0+8)*12 + kq+4];
                al[i][0] = Alp[m0*12 + kq];     al[i][1] = Alp[(m0+8)*12 + kq];
                al[i][2] = Alp[m0*12 + kq+4];   al[i][3] = Alp[(m0+8)*12 + kq+4];
            }
            #pragma unroll
            for (int j = 0; j < 8; j++) {
                int nb = wn + j * 8 + (lane >> 2);
                unsigned bh2[2] = {Whp[nb*12 + kq], Whp[nb*12 + kq+4]};
                unsigned bl2[2] = {Wlp[nb*12 + kq], Wlp[nb*12 + kq+4]};
                #pragma unroll
                for (int i = 0; i < 2; i++) {
                    mma16(acc[i][j], al[i], bh2);
                    mma16(acc[i][j], ah[i], bl2);
                    mma16(acc[i][j], ah[i], bh2);
                }
            }
            __syncthreads();
            if (t + QKSTG - 1 < ntiles) prefetch(t + QKSTG - 1);
            else asm volatile("cp.async.commit_group;");
        }
        #pragma unroll
        for (int j = 0; j < 8; j++) {
            int c = col0 + wn + j * 8 + (lane & 3) * 2;
            float2 bb = *(const float2*)&bias[c];
            #pragma unroll
            for (int i = 0; i < 2; i++) {
                size_t r = row0 + wm + i * 16 + (lane >> 2);
                unsigned h, l;
                splitbf2(acc[i][j][0] + bb.x, acc[i][j][1] + bb.y, h, l);
                Ohi[r * 512 + (c >> 1)] = h;  Olo[r * 512 + (c >> 1)] = l;
                splitbf2(acc[i][j][2] + bb.x, acc[i][j][3] + bb.y, h, l);
                Ohi[(r + 8) * 512 + (c >> 1)] = h;  Olo[(r + 8) * 512 + (c >> 1)] = l;
            }
        }
    } else {
        float* As2 = (float*)smu;            // [VPSTG][128][20]
        float* Ws2 = As2 + VP_AS;
        const int ntiles = DMODEL / 16;

        auto prefetch = [&](int t) {
            int s = t & (VPSTG - 1);
            int k0 = t * 16;
            #pragma unroll
            for (int l = 0; l < 2; l++) {
                int c = tid + l * 256, r = c >> 2, qd = (c & 3) * 4;
                cpasync16(&As2[s*2560 + r*20 + qd], &vin[(size_t)(row0+r)*DMODEL + k0 + qd]);
                cpasync16(&Ws2[s*2560 + r*20 + qd], &wv[(size_t)(col0+r)*DMODEL + k0 + qd]);
            }
            asm volatile("cp.async.commit_group;");
        };
        #pragma unroll
        for (int t = 0; t < VPSTG - 1; t++) prefetch(t);

        float acc[2][8][4] = {};
        for (int t = 0; t < ntiles; t++) {
            int s = t & (VPSTG - 1);
            asm volatile("cp.async.wait_group %0;" :: "n"(VPSTG - 2));
            __syncthreads();
            const float* Ap = &As2[s*2560];
            const float* Wp = &Ws2[s*2560];
            #pragma unroll
            for (int kk = 0; kk < 16; kk += 8) {
                const int kr = kk + (lane & 3), m0 = wm + (lane >> 2);
                unsigned af[2][4];
                #pragma unroll
                for (int i = 0; i < 2; i++) {
                    af[i][0] = __float_as_uint(Ap[(m0+i*16)*20 + kr]);
                    af[i][1] = __float_as_uint(Ap[(m0+i*16+8)*20 + kr]);
                    af[i][2] = __float_as_uint(Ap[(m0+i*16)*20 + kr+4]);
                    af[i][3] = __float_as_uint(Ap[(m0+i*16+8)*20 + kr+4]);
                }
                #pragma unroll
                for (int j = 0; j < 8; j++) {
                    int nb = wn + j * 8 + (lane >> 2);
                    unsigned bf[2] = {__float_as_uint(Wp[nb*20 + kr]),
                                      __float_as_uint(Wp[nb*20 + kr+4])};
                    mma8(acc[0][j], af[0], bf);
                    mma8(acc[1][j], af[1], bf);
                }
            }
            __syncthreads();
            if (t + VPSTG - 1 < ntiles) prefetch(t + VPSTG - 1);
            else asm volatile("cp.async.commit_group;");
        }
        const int rg = lane >> 2;
        const bool evenrow = (rg & 1) == 0;
        #pragma unroll
        for (int j = 0; j < 8; j++) {
            int c = col0 + wn + j * 8 + (lane & 3) * 2;
            float2 bb = *(const float2*)&bv[c];
            #pragma unroll
            for (int i = 0; i < 2; i++) {
                float x0 = acc[i][j][0] + bb.x, y0 = acc[i][j][1] + bb.y;
                float x1 = acc[i][j][2] + bb.x, y1 = acc[i][j][3] + bb.y;
                float px0 = __shfl_down_sync(0xffffffffu, x0, 4);
                float py0 = __shfl_down_sync(0xffffffffu, y0, 4);
                float px1 = __shfl_down_sync(0xffffffffu, x1, 4);
                float py1 = __shfl_down_sync(0xffffffffu, y1, 4);
                if (evenrow) {
                    int r = row0 + wm + i * 16 + rg;
                    size_t t0 = (size_t)(r >> 1);
                    size_t t1 = (size_t)((r + 8) >> 1);
                    uint2 o0 = make_uint2(packh2(x0, px0), packh2(y0, py0));
                    uint2 o1 = make_uint2(packh2(x1, px1), packh2(y1, py1));
                    *(uint2*)&gv16[t0 * DMODEL + c] = o0;
                    *(uint2*)&gv16[t1 * DMODEL + c] = o1;
                }
            }
        }
    }
}

// ---------------------------------------------------------------------------
// O projection: single ctx input, cp.async 4-stage, 2 streams.
// ---------------------------------------------------------------------------
__global__ __launch_bounds__(256, 2)
void gemm_o_tf32(const float* __restrict__ ctx, const float* __restrict__ W,
                 const float* __restrict__ bias, float* __restrict__ C) {
    extern __shared__ float osm[];
    float* As0 = osm;
    float* Ws2 = osm + OP_AS;
    const int tid = threadIdx.x, lane = tid & 31, warp = tid >> 5;
    const int wm = (warp & 3) * 32, wn = (warp >> 2) * 64;
    const int row0 = blockIdx.y * 128, col0 = blockIdx.x * 128;
    const int ntiles = DMODEL / 16;

    auto prefetch = [&](int t) {
        int s = t & (OPSTG - 1);
        int k0 = t * 16;
        #pragma unroll
        for (int l = 0; l < 2; l++) {
            int c = tid + l * 256, r = c >> 2, qd = (c & 3) * 4;
            cpasync16(&As0[s*2560 + r*20 + qd], &ctx[(size_t)(row0+r)*DMODEL + k0 + qd]);
            cpasync16(&Ws2[s*2560 + r*20 + qd], &W[(size_t)(col0+r)*DMODEL + k0 + qd]);
        }
        asm volatile("cp.async.commit_group;");
    };
    #pragma unroll
    for (int t = 0; t < OPSTG - 1; t++) prefetch(t);

    float acc[2][8][4] = {};
    for (int t = 0; t < ntiles; t++) {
        int s = t & (OPSTG - 1);
        asm volatile("cp.async.wait_group %0;" :: "n"(OPSTG - 2));
        __syncthreads();
        const float* A0 = &As0[s*2560];
        const float* Wp = &Ws2[s*2560];
        #pragma unroll
        for (int kk = 0; kk < 16; kk += 8) {
            const int kr = kk + (lane & 3), m0 = wm + (lane >> 2);
            unsigned af[2][4];
            #pragma unroll
            for (int i = 0; i < 2; i++) {
                int r0 = (m0 + i*16) * 20, r1 = (m0 + i*16 + 8) * 20;
                af[i][0] = __float_as_uint(A0[r0 + kr]);
                af[i][1] = __float_as_uint(A0[r1 + kr]);
                af[i][2] = __float_as_uint(A0[r0 + kr+4]);
                af[i][3] = __float_as_uint(A0[r1 + kr+4]);
            }
            #pragma unroll
            for (int j = 0; j < 8; j++) {
                int nb = wn + j * 8 + (lane >> 2);
                unsigned bf[2] = {__float_as_uint(Wp[nb*20 + kr]),
                                  __float_as_uint(Wp[nb*20 + kr+4])};
                mma8(acc[0][j], af[0], bf);
                mma8(acc[1][j], af[1], bf);
            }
        }
        __syncthreads();
        if (t + OPSTG - 1 < ntiles) prefetch(t + OPSTG - 1);
        else asm volatile("cp.async.commit_group;");
    }
    #pragma unroll
    for (int j = 0; j < 8; j++) {
        int c = col0 + wn + j * 8 + (lane & 3) * 2;
        float2 bb = *(const float2*)&bias[c];
        #pragma unroll
        for (int i = 0; i < 2; i++) {
            size_t r = row0 + wm + i * 16 + (lane >> 2);
            float2 o0 = {acc[i][j][0] + bb.x, acc[i][j][1] + bb.y};
            float2 o1 = {acc[i][j][2] + bb.x, acc[i][j][3] + bb.y};
            *(float2*)&C[r * DMODEL + c]       = o0;
            *(float2*)&C[(r + 8) * DMODEL + c] = o1;
        }
    }
}

// ---------------------------------------------------------------------------
// Fused scores (3xBF16) + uint8 mask + exp -> fp16 unnorm P + rowsum partials.
// grid (32 bh, NKT ktile, 16 qtile).
// ---------------------------------------------------------------------------
__global__ __launch_bounds__(256, 2)
void scores_exp(const unsigned* __restrict__ opk,
                const unsigned char* __restrict__ mask8,
                unsigned* __restrict__ p16, float* __restrict__ partial) {
    extern __shared__ unsigned dsm[];
    unsigned* Qh = dsm;                    // [128][36]
    unsigned* Ql = Qh + 128*36;
    unsigned* Kh = Ql + 128*36;
    unsigned* Kl = Kh + 128*36;
    float* sums = (float*)(Kl + 128*36);

    const int tid = threadIdx.x, lane = tid & 31, warp = tid >> 5;
    const int wm = (warp & 3) * 32, wn = (warp >> 2) * 64, kq = lane & 3;
    const int bh_i = blockIdx.x, b = bh_i >> 4, h = bh_i & 15;
    const int c0 = blockIdx.y * 128, q0 = blockIdx.z * 128;
    const unsigned* Qhi = opk;
    const unsigned* Qlo = opk + PKA;
    const unsigned* Khi = opk + 2 * PKA;
    const unsigned* Klo = opk + 3 * PKA;
    const int hoff = h * 32;

    #pragma unroll
    for (int l = 0; l < 4; l++) {
        int idx = tid + l * 256, r = idx >> 3, kp4 = (idx & 7) * 4;
        size_t qoff = (size_t)(b * SEQ + q0 + r) * 512 + hoff + kp4;
        size_t koff = (size_t)(b * SEQ + c0 + r) * 512 + hoff + kp4;
        cpasync16(&Qh[r*36 + kp4], &Qhi[qoff]);
        cpasync16(&Ql[r*36 + kp4], &Qlo[qoff]);
        cpasync16(&Kh[r*36 + kp4], &Khi[koff]);
        cpasync16(&Kl[r*36 + kp4], &Klo[koff]);
    }
    asm volatile("cp.async.commit_group;");
    asm volatile("cp.async.wait_group 0;");
    __syncthreads();

    float acc[2][8][4] = {};
    #pragma unroll
    for (int kk = 0; kk < 32; kk += 8) {
        unsigned ah[2][4], al[2][4];
        #pragma unroll
        for (int i = 0; i < 2; i++) {
            int m0 = wm + i * 16 + (lane >> 2);
            ah[i][0] = Qh[m0*36 + kk+kq];     ah[i][1] = Qh[(m0+8)*36 + kk+kq];
            ah[i][2] = Qh[m0*36 + kk+kq+4];   ah[i][3] = Qh[(m0+8)*36 + kk+kq+4];
            al[i][0] = Ql[m0*36 + kk+kq];     al[i][1] = Ql[(m0+8)*36 + kk+kq];
            al[i][2] = Ql[m0*36 + kk+kq+4];   al[i][3] = Ql[(m0+8)*36 + kk+kq+4];
        }
        #pragma unroll
        for (int j = 0; j < 8; j++) {
            int nb = wn + j * 8 + (lane >> 2);
            unsigned bh2[2] = {Kh[nb*36 + kk+kq], Kh[nb*36 + kk+kq+4]};
            unsigned bl2[2] = {Kl[nb*36 + kk+kq], Kl[nb*36 + kk+kq+4]};
            #pragma unroll
            for (int i = 0; i < 2; i++) {
                mma16(acc[i][j], al[i], bh2);
                mma16(acc[i][j], ah[i], bl2);
                mma16(acc[i][j], ah[i], bh2);
            }
        }
    }

    const unsigned char* mrow = mask8 + (size_t)b * SEQ * SEQ;
    unsigned* out16 = p16 + (size_t)bh_i * SEQ * (SEQ / 2);
    float rs[2][2] = {};
    #pragma unroll
    for (int j = 0; j < 8; j++) {
        int c = c0 + wn + j * 8 + (lane & 3) * 2;
        int kp = c >> 1;
        #pragma unroll
        for (int i = 0; i < 2; i++) {
            size_t r = q0 + wm + i * 16 + (lane >> 2);
            uchar2 m0v = *(const uchar2*)&mrow[r * SEQ + c];
            uchar2 m1v = *(const uchar2*)&mrow[(r + 8) * SEQ + c];
            float2 o0, o1;
            o0.x = m0v.x ? __expf(acc[i][j][0] * 0.125f) : 0.f;
            o0.y = m0v.y ? __expf(acc[i][j][1] * 0.125f) : 0.f;
            o1.x = m1v.x ? __expf(acc[i][j][2] * 0.125f) : 0.f;
            o1.y = m1v.y ? __expf(acc[i][j][3] * 0.125f) : 0.f;
            __stcs(&out16[r * (SEQ/2) + kp],       packh2(o0.x, o0.y));
            __stcs(&out16[(r + 8) * (SEQ/2) + kp], packh2(o1.x, o1.y));
            rs[i][0] += o0.x + o0.y;
            rs[i][1] += o1.x + o1.y;
        }
    }
    #pragma unroll
    for (int i = 0; i < 2; i++)
        #pragma unroll
        for (int hh = 0; hh < 2; hh++) {
            float v = rs[i][hh];
            v += __shfl_xor_sync(0xffffffffu, v, 1);
            v += __shfl_xor_sync(0xffffffffu, v, 2);
            if ((lane & 3) == 0)
                sums[(warp >> 2) * 128 + wm + i * 16 + hh * 8 + (lane >> 2)] = v;
        }
    __syncthreads();
    if (tid < 128) {
        float tot = sums[tid] + sums[128 + tid];
        partial[((size_t)bh_i * SEQ + q0 + tid) * NKT + blockIdx.y] = tot;
    }
}

// ---------------------------------------------------------------------------
// Fused PV (f16 mma, full-K), cp.async 3-stage. grid (16 qtile, 32 bh).
// ---------------------------------------------------------------------------
__global__ __launch_bounds__(256, 4)
void pv_norm16(const unsigned* __restrict__ p16, const unsigned* __restrict__ gv16,
               const float* __restrict__ partial, float* __restrict__ attn,
               float* __restrict__ ctx) {
    extern __shared__ unsigned pvs[];
    unsigned* Ps = pvs;                      // [PV16STG][128][20]
    unsigned* Vs = pvs + PV16_PS;            // [PV16STG][16][68]
    float* inv_s = (float*)(pvs + PV16_PS + PV16_VS);

    const int tid = threadIdx.x, lane = tid & 31, warp = tid >> 5;
    const int wm = (warp & 3) * 32, wn = (warp >> 2) * 32, kq = lane & 3;
    const int bh_i = blockIdx.y, b = bh_i >> 4, h = bh_i & 15;
    const unsigned* P16 = p16 + (size_t)bh_i * SEQ * (SEQ / 2);
    float* Pout = attn + (size_t)bh_i * SEQ * SEQ;
    const unsigned* V16 = gv16 + (size_t)b * (SEQ / 2) * DMODEL + h * DHEAD;
    float* Cc = ctx + (size_t)b * SEQ * DMODEL + h * DHEAD;
    const int q0 = blockIdx.x * 128;
    const int ntiles = SEQ / 32;             // 64 tiles of 32 keys

    auto prefetch = [&](int t) {
        int s = t % PV16STG;
        int kp0 = t * 16;
        #pragma unroll
        for (int l = 0; l < 2; l++) {
            int idx = tid + l * 256, r = idx >> 2, k4 = (idx & 3) * 4;
            cpasync16(&Ps[s*2560 + r*20 + k4], &P16[(size_t)(q0+r)*(SEQ/2) + kp0 + k4]);
        }
        {
            int kp = tid >> 4, n4 = (tid & 15) * 4;
            cpasync16(&Vs[s*1088 + kp*68 + n4], &V16[(size_t)(kp0+kp)*DMODEL + n4]);
        }
        asm volatile("cp.async.commit_group;");
    };
    #pragma unroll
    for (int t = 0; t < PV16STG - 1; t++) prefetch(t);

    if (tid < 128) {
        const float4* pp = (const float4*)&partial[((size_t)bh_i * SEQ + q0 + tid) * NKT];
        float4 p0 = pp[0], p1 = pp[1], p2 = pp[2], p3 = pp[3];
        float s = ((p0.x + p0.y) + (p0.z + p0.w)) + ((p1.x + p1.y) + (p1.z + p1.w))
                + ((p2.x + p2.y) + (p2.z + p2.w)) + ((p3.x + p3.y) + (p3.z + p3.w));
        inv_s[tid] = 1.0f / s;
    }

    float acc[2][4][4] = {};
    for (int t = 0; t < ntiles; t++) {
        int s = t % PV16STG;
        asm volatile("cp.async.wait_group %0;" :: "n"(PV16STG - 2));
        __syncthreads();
        const unsigned* Pp = &Ps[s*2560];
        const unsigned* Vp = &Vs[s*1088];
        #pragma unroll
        for (int kk = 0; kk < 16; kk += 8) {
            unsigned af[2][4];
            #pragma unroll
            for (int i = 0; i < 2; i++) {
                int m0 = wm + i * 16 + (lane >> 2);
                af[i][0] = Pp[m0*20 + kk+kq];     af[i][1] = Pp[(m0+8)*20 + kk+kq];
                af[i][2] = Pp[m0*20 + kk+kq+4];   af[i][3] = Pp[(m0+8)*20 + kk+kq+4];
            }
            #pragma unroll
            for (int j = 0; j < 4; j++) {
                int nb = wn + j * 8 + (lane >> 2);
                unsigned bf[2] = {Vp[(kk+kq)*68 + nb], Vp[(kk+kq+4)*68 + nb]};
                mma16h(acc[0][j], af[0], bf);
                mma16h(acc[1][j], af[1], bf);
            }
        }
        {
            int kcol = t * 32;
            #pragma unroll
            for (int l = 0; l < 2; l++) {
                int idx = tid + l * 256, r = idx >> 2, k4 = (idx & 3) * 4;
                float sc = inv_s[r];
                float4 o0, o1;
                float2 f;
                f = unpackh2(Pp[r*20 + k4 + 0]); o0.x = f.x * sc; o0.y = f.y * sc;
                f = unpackh2(Pp[r*20 + k4 + 1]); o0.z = f.x * sc; o0.w = f.y * sc;
                f = unpackh2(Pp[r*20 + k4 + 2]); o1.x = f.x * sc; o1.y = f.y * sc;
                f = unpackh2(Pp[r*20 + k4 + 3]); o1.z = f.x * sc; o1.w = f.y * sc;
                size_t base = (size_t)(q0 + r) * SEQ + kcol + k4 * 2;
                __stcs((float4*)&Pout[base],     o0);
                __stcs((float4*)&Pout[base + 4], o1);
            }
        }
        __syncthreads();
        if (t + PV16STG - 1 < ntiles) prefetch(t + PV16STG - 1);
        else asm volatile("cp.async.commit_group;");
    }
    #pragma unroll
    for (int j = 0; j < 4; j++) {
        int c = wn + j * 8 + (lane & 3) * 2;
        #pragma unroll
        for (int i = 0; i < 2; i++) {
            int rl = wm + i * 16 + (lane >> 2);
            float sc0 = inv_s[rl], sc1 = inv_s[rl + 8];
            size_t r = q0 + rl;
            float2 o0 = {acc[i][j][0] * sc0, acc[i][j][1] * sc0};
            float2 o1 = {acc[i][j][2] * sc1, acc[i][j][3] * sc1};
            *(float2*)&Cc[r * DMODEL + c]       = o0;
            *(float2*)&Cc[(r + 8) * DMODEL + c] = o1;
        }
    }
}

// ---------------------------------------------------------------------------
// Residual + LayerNorm.
// ---------------------------------------------------------------------------
__global__ void ln_kernel(const float* __restrict__ resid,
                          const float* __restrict__ x,
                          const float* __restrict__ gamma,
                          const float* __restrict__ beta,
                          float* __restrict__ out) {
    const size_t row = blockIdx.x;
    const float4* xr = reinterpret_cast<const float4*>(x + row * DMODEL);
    const float4* rr = reinterpret_cast<const float4*>(resid + row * DMODEL);
    const int t = threadIdx.x;
    __shared__ float sred[8];

    float4 a = rr[t], bv = xr[t];
    float4 v = {a.x + bv.x, a.y + bv.y, a.z + bv.z, a.w + bv.w};
    float s = v.x + v.y + v.z + v.w;
    #pragma unroll
    for (int o = 16; o > 0; o >>= 1) s += __shfl_xor_sync(0xffffffffu, s, o);
    if ((t & 31) == 0) sred[t >> 5] = s;
    __syncthreads();
    float tot = 0.f;
    #pragma unroll
    for (int i = 0; i < 8; i++) tot += sred[i];
    const float mu = tot * (1.0f / DMODEL);
    __syncthreads();

    float dx = v.x - mu, dy = v.y - mu, dz = v.z - mu, dw = v.w - mu;
    float sq = dx*dx + dy*dy + dz*dz + dw*dw;
    #pragma unroll
    for (int o = 16; o > 0; o >>= 1) sq += __shfl_xor_sync(0xffffffffu, sq, o);
    if ((t & 31) == 0) sred[t >> 5] = sq;
    __syncthreads();
    float tot2 = 0.f;
    #pragma unroll
    for (int i = 0; i < 8; i++) tot2 += sred[i];
    const float inv = rsqrtf(tot2 * (1.0f / DMODEL) + 1e-5f);

    float4 g = reinterpret_cast<const float4*>(gamma)[t];
    float4 be = reinterpret_cast<const float4*>(beta)[t];
    float4 o;
    o.x = dx * inv * g.x + be.x;
    o.y = dy * inv * g.y + be.y;
    o.z = dz * inv * g.z + be.z;
    o.w = dw * inv * g.w + be.w;
    reinterpret_cast<float4*>(out + row * DMODEL)[t] = o;
}

// ---------------------------------------------------------------------------
extern "C" void kernel_launch(void* const* d_in, const int* in_sizes, int n_in,
                              void* d_out, int out_size) {
    const float* q     = (const float*)d_in[0];
    const float* k     = (const float*)d_in[1];
    const float* v     = (const float*)d_in[2];
    const int*   mask  = (const int*)  d_in[3];
    const float* wq    = (const float*)d_in[4];
    const float* bq    = (const float*)d_in[5];
    const float* wk    = (const float*)d_in[6];
    const float* bk    = (const float*)d_in[7];
    const float* wv    = (const float*)d_in[8];
    const float* bv    = (const float*)d_in[9];
    const float* wo    = (const float*)d_in[10];
    const float* bo    = (const float*)d_in[11];
    const float* gamma = (const float*)d_in[12];
    const float* beta  = (const float*)d_in[13];

    float* out  = (float*)d_out;
    float* attn = out + ATT_OFF;

    void* sp = nullptr;
    cudaGetSymbolAddress(&sp, g_scratch);
    float* go      = (float*)sp;
    float* ctx     = go + PS;
    float* partial = ctx + PS;
    unsigned* ipk  = (unsigned*)(partial + PARTIAL_SZ);   // q,k hi/lo (4*PKA)
    unsigned* wpk  = ipk + 4 * PKA;                        // wq,wk hi/lo (4*PKW)
    unsigned* opk  = wpk + 4 * PKW;                        // gq,gk hi/lo (4*PKA)
    unsigned* gv16 = opk + 4 * PKA;                        // fp16 V kpairs
    unsigned* p16  = gv16 + GV16_SZ;                       // fp16 unnorm P
    unsigned char* mask8 = (unsigned char*)(p16 + P16_SZ); // uint8 mask

    cudaFuncSetAttribute(scores_exp,  cudaFuncAttributeMaxDynamicSharedMemorySize, SC_SMEM);
    cudaFuncSetAttribute(pv_norm16,   cudaFuncAttributeMaxDynamicSharedMemorySize, PV16_SMEM);
    cudaFuncSetAttribute(gemm_o_tf32, cudaFuncAttributeMaxDynamicSharedMemorySize, OP_SMEM);
    cudaFuncSetAttribute(gemm_proj,   cudaFuncAttributeMaxDynamicSharedMemorySize, PROJ_SMEM);

    dim3 gPre((unsigned)((PKA / 2 + 255) / 256), 4);
    prepack_all<<<gPre, 256>>>(q, k, wq, wk, ipk, wpk);

    prepack_mask<<<(unsigned)(M8_W / 256), 256>>>(mask, mask8);

    dim3 gProj3(DMODEL / 128, MROWS / 128, 3);          // (8, 32, 3): q, k, v
    gemm_proj<<<gProj3, 256, PROJ_SMEM>>>(ipk, wpk, v, wv, bq, bk, bv, opk, gv16);

    dim3 gScores(BATCH * NHEADS, NKT, SEQ / 128);       // (32, 16, 16)
    scores_exp<<<gScores, 256, SC_SMEM>>>(opk, mask8, p16, partial);

    dim3 gPV(SEQ / 128, BATCH * NHEADS);                // (16, 32)
    pv_norm16<<<gPV, 256, PV16_SMEM>>>(p16, gv16, partial, attn, ctx);

    dim3 gProj(DMODEL / 128, MROWS / 128);              // (8, 32)
    gemm_o_tf32<<<gProj, 256, OP_SMEM>>>(ctx, wo, bo, go);

    ln_kernel<<<MROWS, 256>>>(q, go, gamma, beta, out);
}

// round 17
// speedup vs baseline: 1.2584x; 1.1397x over previous
#include <cuda_runtime.h>
#include <cuda_bf16.h>
#include <cuda_fp16.h>
#include <math.h>

#define BATCH 2
#define SEQ   2048
#define DMODEL 1024
#define NHEADS 16
#define DHEAD  64
#define MROWS (BATCH*SEQ)                    // 4096
#define ATT_OFF ((size_t)BATCH*SEQ*DMODEL)
#define NKT 16
#define OPSTG 4
#define QKSTG 4
#define VPSTG 4
#define PV16STG 3

#define PS   ((size_t)MROWS * 1024)
#define PKA  ((size_t)MROWS * 512)           // u32 kpairs per 4096x1024 tensor
#define PKW  ((size_t)DMODEL * 512)
#define PARTIAL_SZ ((size_t)BATCH * NHEADS * SEQ * NKT)
#define P16_SZ ((size_t)BATCH * NHEADS * SEQ * (SEQ/2))
#define GV16_SZ ((size_t)(MROWS/2) * DMODEL)
#define M8_W   ((size_t)BATCH * SEQ * SEQ / 4)

// go, ctx, partial, ipk(4*PKA), wpk(4*PKW), opk16(2*PKA), gv16, p16, mask8
__device__ float g_scratch[2ull * PS + PARTIAL_SZ + 8ull * PKA + 4ull * PKW
                           + GV16_SZ + P16_SZ + M8_W];

// scores smem: Q16/K16 [128][36] u32 + sums[2][128]
#define SC_SMEM (2 * 128 * 36 * 4 + 256 * 4)
// pv16 smem
#define PV16_PS (PV16STG * 128 * 20)
#define PV16_VS (PV16STG * 16 * 68)
#define PV16_SMEM ((PV16_PS + PV16_VS + 128) * 4)
// oproj smem
#define OP_AS   (OPSTG * 128 * 20)
#define OP_SMEM (2 * OP_AS * 4)
// fused proj smem
#define QK_ARR  (QKSTG * 128 * 12)
#define VP_AS   (VPSTG * 128 * 20)
#define PROJ_SMEM (4 * QK_ARR * 4)

// ---------------------------------------------------------------------------
__device__ __forceinline__ void mma8(float* d, const unsigned* a, const unsigned* b) {
    asm volatile(
        "mma.sync.aligned.m16n8k8.row.col.f32.tf32.tf32.f32 "
        "{%0,%1,%2,%3}, {%4,%5,%6,%7}, {%8,%9}, {%0,%1,%2,%3};"
        : "+f"(d[0]), "+f"(d[1]), "+f"(d[2]), "+f"(d[3])
        : "r"(a[0]), "r"(a[1]), "r"(a[2]), "r"(a[3]), "r"(b[0]), "r"(b[1]));
}
__device__ __forceinline__ void mma16(float* d, const unsigned* a, const unsigned* b) {
    asm volatile(
        "mma.sync.aligned.m16n8k16.row.col.f32.bf16.bf16.f32 "
        "{%0,%1,%2,%3}, {%4,%5,%6,%7}, {%8,%9}, {%0,%1,%2,%3};"
        : "+f"(d[0]), "+f"(d[1]), "+f"(d[2]), "+f"(d[3])
        : "r"(a[0]), "r"(a[1]), "r"(a[2]), "r"(a[3]), "r"(b[0]), "r"(b[1]));
}
__device__ __forceinline__ void mma16h(float* d, const unsigned* a, const unsigned* b) {
    asm volatile(
        "mma.sync.aligned.m16n8k16.row.col.f32.f16.f16.f32 "
        "{%0,%1,%2,%3}, {%4,%5,%6,%7}, {%8,%9}, {%0,%1,%2,%3};"
        : "+f"(d[0]), "+f"(d[1]), "+f"(d[2]), "+f"(d[3])
        : "r"(a[0]), "r"(a[1]), "r"(a[2]), "r"(a[3]), "r"(b[0]), "r"(b[1]));
}
__device__ __forceinline__ void splitbf2(float x, float y, unsigned& hi, unsigned& lo) {
    __nv_bfloat16 hx = __float2bfloat16_rn(x);
    __nv_bfloat16 hy = __float2bfloat16_rn(y);
    __nv_bfloat16 lx = __float2bfloat16_rn(x - __bfloat162float(hx));
    __nv_bfloat16 ly = __float2bfloat16_rn(y - __bfloat162float(hy));
    hi = (unsigned)__bfloat16_as_ushort(hx) | ((unsigned)__bfloat16_as_ushort(hy) << 16);
    lo = (unsigned)__bfloat16_as_ushort(lx) | ((unsigned)__bfloat16_as_ushort(ly) << 16);
}
__device__ __forceinline__ unsigned packh2(float x, float y) {
    __half2 h = __floats2half2_rn(x, y);
    return *reinterpret_cast<unsigned*>(&h);
}
__device__ __forceinline__ float2 unpackh2(unsigned u) {
    __half2 h = *reinterpret_cast<__half2*>(&u);
    return __half22float2(h);
}
__device__ __forceinline__ void cpasync16(void* sm, const void* gm) {
    unsigned a = (unsigned)__cvta_generic_to_shared(sm);
    asm volatile("cp.async.cg.shared.global [%0], [%1], 16;" :: "r"(a), "l"(gm));
}

// ---------------------------------------------------------------------------
// Prepack q,k,wq,wk -> bf16 (hi,lo) kpair arrays (projection operands).
// ---------------------------------------------------------------------------
__global__ void prepack_all(const float* __restrict__ q, const float* __restrict__ k,
                            const float* __restrict__ wq, const float* __restrict__ wk,
                            unsigned* __restrict__ ipk, unsigned* __restrict__ wpk) {
    const int z = blockIdx.y;
    const int i = blockIdx.x * 256 + threadIdx.x;
    const float* src;
    unsigned *hi, *lo;
    int half;
    if (z < 2) {
        src = z ? k : q;
        hi = ipk + (size_t)z * 2 * PKA; lo = hi + PKA;
        half = (int)(PKA / 2);
    } else {
        src = (z == 2) ? wq : wk;
        hi = wpk + (size_t)(z - 2) * 2 * PKW; lo = hi + PKW;
        half = (int)(PKW / 2);
    }
    if (i < half) {
        float4 x = ((const float4*)src)[i];
        unsigned h0, l0, h1, l1;
        splitbf2(x.x, x.y, h0, l0);
        splitbf2(x.z, x.w, h1, l1);
        ((uint2*)hi)[i] = make_uint2(h0, h1);
        ((uint2*)lo)[i] = make_uint2(l0, l1);
    }
}

// ---------------------------------------------------------------------------
// Prepack mask int32 -> uint8.
// ---------------------------------------------------------------------------
__global__ void prepack_mask(const int* __restrict__ m, unsigned char* __restrict__ m8) {
    size_t i = (size_t)blockIdx.x * 256 + threadIdx.x;
    int4 v = ((const int4*)m)[i];
    uchar4 o;
    o.x = (unsigned char)v.x; o.y = (unsigned char)v.y;
    o.z = (unsigned char)v.z; o.w = (unsigned char)v.w;
    ((uchar4*)m8)[i] = o;
}

// ---------------------------------------------------------------------------
// Fused projections. z=0 q, z=1 k (3xBF16 mainloop, fp16 kpair out);
// z=2 v (1xTF32, fp16 kpair gv16 out). cp.async pipelined.
// ---------------------------------------------------------------------------
__global__ __launch_bounds__(256, 2)
void gemm_proj(const unsigned* __restrict__ apk, const unsigned* __restrict__ wpk,
               const float* __restrict__ vin, const float* __restrict__ wv,
               const float* __restrict__ bq, const float* __restrict__ bk,
               const float* __restrict__ bv, unsigned* __restrict__ opk16,
               unsigned* __restrict__ gv16) {
    extern __shared__ unsigned smu[];
    const int z = blockIdx.z;
    const int tid = threadIdx.x, lane = tid & 31, warp = tid >> 5;
    const int wm = (warp & 3) * 32, wn = (warp >> 2) * 64, kq = lane & 3;
    const int row0 = blockIdx.y * 128, col0 = blockIdx.x * 128;

    if (z < 2) {
        unsigned* Ah = smu;
        unsigned* Al = smu + QK_ARR;
        unsigned* Wh = smu + 2 * QK_ARR;
        unsigned* Wl = smu + 3 * QK_ARR;
        const unsigned* Ahi = apk + (size_t)z * 2 * PKA;
        const unsigned* Alo = Ahi + PKA;
        const unsigned* Whi = wpk + (size_t)z * 2 * PKW;
        const unsigned* Wlo = Whi + PKW;
        unsigned* O16 = opk16 + (size_t)z * PKA;
        const float* bias = z ? bk : bq;
        const int ntiles = 512 / 8;

        const int pr = tid >> 1, pk4 = (tid & 1) * 4;
        auto prefetch = [&](int t) {
            int s = t & (QKSTG - 1);
            int kp0 = t * 8;
            cpasync16(&Ah[s*1536 + pr*12 + pk4], &Ahi[(size_t)(row0+pr)*512 + kp0 + pk4]);
            cpasync16(&Al[s*1536 + pr*12 + pk4], &Alo[(size_t)(row0+pr)*512 + kp0 + pk4]);
            cpasync16(&Wh[s*1536 + pr*12 + pk4], &Whi[(size_t)(col0+pr)*512 + kp0 + pk4]);
            cpasync16(&Wl[s*1536 + pr*12 + pk4], &Wlo[(size_t)(col0+pr)*512 + kp0 + pk4]);
            asm volatile("cp.async.commit_group;");
        };
        #pragma unroll
        for (int t = 0; t < QKSTG - 1; t++) prefetch(t);

        float acc[2][8][4] = {};
        for (int t = 0; t < ntiles; t++) {
            int s = t & (QKSTG - 1);
            asm volatile("cp.async.wait_group %0;" :: "n"(QKSTG - 2));
            __syncthreads();
            const unsigned* Ahp = &Ah[s*1536];
            const unsigned* Alp = &Al[s*1536];
            const unsigned* Whp = &Wh[s*1536];
            const unsigned* Wlp = &Wl[s*1536];
            unsigned ah[2][4], al[2][4];
            #pragma unroll
            for (int i = 0; i < 2; i++) {
                int m0 = wm + i * 16 + (lane >> 2);
                ah[i][0] = Ahp[m0*12 + kq];     ah[i][1] = Ahp[(m0+8)*12 + kq];
                ah[i][2] = Ahp[m0*12 + kq+4];   ah[i][3] = Ahp[(m0+8)*12 + kq+4];
                al[i][0] = Alp[m0*12 + kq];     al[i][1] = Alp[(m0+8)*12 + kq];
                al[i][2] = Alp[m0*12 + kq+4];   al[i][3] = Alp[(m0+8)*12 + kq+4];
            }
            #pragma unroll
            for (int j = 0; j < 8; j++) {
                int nb = wn + j * 8 + (lane >> 2);
                unsigned bh2[2] = {Whp[nb*12 + kq], Whp[nb*12 + kq+4]};
                unsigned bl2[2] = {Wlp[nb*12 + kq], Wlp[nb*12 + kq+4]};
                #pragma unroll
                for (int i = 0; i < 2; i++) {
                    mma16(acc[i][j], al[i], bh2);
                    mma16(acc[i][j], ah[i], bl2);
                    mma16(acc[i][j], ah[i], bh2);
                }
            }
            __syncthreads();
            if (t + QKSTG - 1 < ntiles) prefetch(t + QKSTG - 1);
            else asm volatile("cp.async.commit_group;");
        }
        #pragma unroll
        for (int j = 0; j < 8; j++) {
            int c = col0 + wn + j * 8 + (lane & 3) * 2;
            float2 bb = *(const float2*)&bias[c];
            #pragma unroll
            for (int i = 0; i < 2; i++) {
                size_t r = row0 + wm + i * 16 + (lane >> 2);
                O16[r * 512 + (c >> 1)]       = packh2(acc[i][j][0] + bb.x, acc[i][j][1] + bb.y);
                O16[(r + 8) * 512 + (c >> 1)] = packh2(acc[i][j][2] + bb.x, acc[i][j][3] + bb.y);
            }
        }
    } else {
        float* As2 = (float*)smu;            // [VPSTG][128][20]
        float* Ws2 = As2 + VP_AS;
        const int ntiles = DMODEL / 16;

        auto prefetch = [&](int t) {
            int s = t & (VPSTG - 1);
            int k0 = t * 16;
            #pragma unroll
            for (int l = 0; l < 2; l++) {
                int c = tid + l * 256, r = c >> 2, qd = (c & 3) * 4;
                cpasync16(&As2[s*2560 + r*20 + qd], &vin[(size_t)(row0+r)*DMODEL + k0 + qd]);
                cpasync16(&Ws2[s*2560 + r*20 + qd], &wv[(size_t)(col0+r)*DMODEL + k0 + qd]);
            }
            asm volatile("cp.async.commit_group;");
        };
        #pragma unroll
        for (int t = 0; t < VPSTG - 1; t++) prefetch(t);

        float acc[2][8][4] = {};
        for (int t = 0; t < ntiles; t++) {
            int s = t & (VPSTG - 1);
            asm volatile("cp.async.wait_group %0;" :: "n"(VPSTG - 2));
            __syncthreads();
            const float* Ap = &As2[s*2560];
            const float* Wp = &Ws2[s*2560];
            #pragma unroll
            for (int kk = 0; kk < 16; kk += 8) {
                const int kr = kk + (lane & 3), m0 = wm + (lane >> 2);
                unsigned af[2][4];
                #pragma unroll
                for (int i = 0; i < 2; i++) {
                    af[i][0] = __float_as_uint(Ap[(m0+i*16)*20 + kr]);
                    af[i][1] = __float_as_uint(Ap[(m0+i*16+8)*20 + kr]);
                    af[i][2] = __float_as_uint(Ap[(m0+i*16)*20 + kr+4]);
                    af[i][3] = __float_as_uint(Ap[(m0+i*16+8)*20 + kr+4]);
                }
                #pragma unroll
                for (int j = 0; j < 8; j++) {
                    int nb = wn + j * 8 + (lane >> 2);
                    unsigned bf[2] = {__float_as_uint(Wp[nb*20 + kr]),
                                      __float_as_uint(Wp[nb*20 + kr+4])};
                    mma8(acc[0][j], af[0], bf);
                    mma8(acc[1][j], af[1], bf);
                }
            }
            __syncthreads();
            if (t + VPSTG - 1 < ntiles) prefetch(t + VPSTG - 1);
            else asm volatile("cp.async.commit_group;");
        }
        const int rg = lane >> 2;
        const bool evenrow = (rg & 1) == 0;
        #pragma unroll
        for (int j = 0; j < 8; j++) {
            int c = col0 + wn + j * 8 + (lane & 3) * 2;
            float2 bb = *(const float2*)&bv[c];
            #pragma unroll
            for (int i = 0; i < 2; i++) {
                float x0 = acc[i][j][0] + bb.x, y0 = acc[i][j][1] + bb.y;
                float x1 = acc[i][j][2] + bb.x, y1 = acc[i][j][3] + bb.y;
                float px0 = __shfl_down_sync(0xffffffffu, x0, 4);
                float py0 = __shfl_down_sync(0xffffffffu, y0, 4);
                float px1 = __shfl_down_sync(0xffffffffu, x1, 4);
                float py1 = __shfl_down_sync(0xffffffffu, y1, 4);
                if (evenrow) {
                    int r = row0 + wm + i * 16 + rg;
                    size_t t0 = (size_t)(r >> 1);
                    size_t t1 = (size_t)((r + 8) >> 1);
                    uint2 o0 = make_uint2(packh2(x0, px0), packh2(y0, py0));
                    uint2 o1 = make_uint2(packh2(x1, px1), packh2(y1, py1));
                    *(uint2*)&gv16[t0 * DMODEL + c] = o0;
                    *(uint2*)&gv16[t1 * DMODEL + c] = o1;
                }
            }
        }
    }
}

// ---------------------------------------------------------------------------
// O projection: single ctx input, cp.async 4-stage, 2 streams.
// ---------------------------------------------------------------------------
__global__ __launch_bounds__(256, 2)
void gemm_o_tf32(const float* __restrict__ ctx, const float* __restrict__ W,
                 const float* __restrict__ bias, float* __restrict__ C) {
    extern __shared__ float osm[];
    float* As0 = osm;
    float* Ws2 = osm + OP_AS;
    const int tid = threadIdx.x, lane = tid & 31, warp = tid >> 5;
    const int wm = (warp & 3) * 32, wn = (warp >> 2) * 64;
    const int row0 = blockIdx.y * 128, col0 = blockIdx.x * 128;
    const int ntiles = DMODEL / 16;

    auto prefetch = [&](int t) {
        int s = t & (OPSTG - 1);
        int k0 = t * 16;
        #pragma unroll
        for (int l = 0; l < 2; l++) {
            int c = tid + l * 256, r = c >> 2, qd = (c & 3) * 4;
            cpasync16(&As0[s*2560 + r*20 + qd], &ctx[(size_t)(row0+r)*DMODEL + k0 + qd]);
            cpasync16(&Ws2[s*2560 + r*20 + qd], &W[(size_t)(col0+r)*DMODEL + k0 + qd]);
        }
        asm volatile("cp.async.commit_group;");
    };
    #pragma unroll
    for (int t = 0; t < OPSTG - 1; t++) prefetch(t);

    float acc[2][8][4] = {};
    for (int t = 0; t < ntiles; t++) {
        int s = t & (OPSTG - 1);
        asm volatile("cp.async.wait_group %0;" :: "n"(OPSTG - 2));
        __syncthreads();
        const float* A0 = &As0[s*2560];
        const float* Wp = &Ws2[s*2560];
        #pragma unroll
        for (int kk = 0; kk < 16; kk += 8) {
            const int kr = kk + (lane & 3), m0 = wm + (lane >> 2);
            unsigned af[2][4];
            #pragma unroll
            for (int i = 0; i < 2; i++) {
                int r0 = (m0 + i*16) * 20, r1 = (m0 + i*16 + 8) * 20;
                af[i][0] = __float_as_uint(A0[r0 + kr]);
                af[i][1] = __float_as_uint(A0[r1 + kr]);
                af[i][2] = __float_as_uint(A0[r0 + kr+4]);
                af[i][3] = __float_as_uint(A0[r1 + kr+4]);
            }
            #pragma unroll
            for (int j = 0; j < 8; j++) {
                int nb = wn + j * 8 + (lane >> 2);
                unsigned bf[2] = {__float_as_uint(Wp[nb*20 + kr]),
                                  __float_as_uint(Wp[nb*20 + kr+4])};
                mma8(acc[0][j], af[0], bf);
                mma8(acc[1][j], af[1], bf);
            }
        }
        __syncthreads();
        if (t + OPSTG - 1 < ntiles) prefetch(t + OPSTG - 1);
        else asm volatile("cp.async.commit_group;");
    }
    #pragma unroll
    for (int j = 0; j < 8; j++) {
        int c = col0 + wn + j * 8 + (lane & 3) * 2;
        float2 bb = *(const float2*)&bias[c];
        #pragma unroll
        for (int i = 0; i < 2; i++) {
            size_t r = row0 + wm + i * 16 + (lane >> 2);
            float2 o0 = {acc[i][j][0] + bb.x, acc[i][j][1] + bb.y};
            float2 o1 = {acc[i][j][2] + bb.x, acc[i][j][3] + bb.y};
            *(float2*)&C[r * DMODEL + c]       = o0;
            *(float2*)&C[(r + 8) * DMODEL + c] = o1;
        }
    }
}

// ---------------------------------------------------------------------------
// Fused scores (single fp16 MMA) + uint8 mask + exp -> fp16 unnorm P
// + fp32 rowsum partials. grid (32 bh, NKT ktile, 16 qtile).
// ---------------------------------------------------------------------------
__global__ __launch_bounds__(256, 2)
void scores_exp(const unsigned* __restrict__ opk16,
                const unsigned char* __restrict__ mask8,
                unsigned* __restrict__ p16, float* __restrict__ partial) {
    extern __shared__ unsigned dsm[];
    unsigned* Q16 = dsm;                   // [128][36]
    unsigned* K16 = Q16 + 128*36;
    float* sums = (float*)(K16 + 128*36);

    const int tid = threadIdx.x, lane = tid & 31, warp = tid >> 5;
    const int wm = (warp & 3) * 32, wn = (warp >> 2) * 64, kq = lane & 3;
    const int bh_i = blockIdx.x, b = bh_i >> 4, h = bh_i & 15;
    const int c0 = blockIdx.y * 128, q0 = blockIdx.z * 128;
    const unsigned* Qg = opk16;
    const unsigned* Kg = opk16 + PKA;
    const int hoff = h * 32;

    #pragma unroll
    for (int l = 0; l < 4; l++) {
        int idx = tid + l * 256, r = idx >> 3, kp4 = (idx & 7) * 4;
        size_t qoff = (size_t)(b * SEQ + q0 + r) * 512 + hoff + kp4;
        size_t koff = (size_t)(b * SEQ + c0 + r) * 512 + hoff + kp4;
        cpasync16(&Q16[r*36 + kp4], &Qg[qoff]);
        cpasync16(&K16[r*36 + kp4], &Kg[koff]);
    }
    asm volatile("cp.async.commit_group;");
    asm volatile("cp.async.wait_group 0;");
    __syncthreads();

    float acc[2][8][4] = {};
    #pragma unroll
    for (int kk = 0; kk < 32; kk += 8) {
        unsigned af[2][4];
        #pragma unroll
        for (int i = 0; i < 2; i++) {
            int m0 = wm + i * 16 + (lane >> 2);
            af[i][0] = Q16[m0*36 + kk+kq];     af[i][1] = Q16[(m0+8)*36 + kk+kq];
            af[i][2] = Q16[m0*36 + kk+kq+4];   af[i][3] = Q16[(m0+8)*36 + kk+kq+4];
        }
        #pragma unroll
        for (int j = 0; j < 8; j++) {
            int nb = wn + j * 8 + (lane >> 2);
            unsigned bf[2] = {K16[nb*36 + kk+kq], K16[nb*36 + kk+kq+4]};
            mma16h(acc[0][j], af[0], bf);
            mma16h(acc[1][j], af[1], bf);
        }
    }

    const unsigned char* mrow = mask8 + (size_t)b * SEQ * SEQ;
    unsigned* out16 = p16 + (size_t)bh_i * SEQ * (SEQ / 2);
    float rs[2][2] = {};
    #pragma unroll
    for (int j = 0; j < 8; j++) {
        int c = c0 + wn + j * 8 + (lane & 3) * 2;
        int kp = c >> 1;
        #pragma unroll
        for (int i = 0; i < 2; i++) {
            size_t r = q0 + wm + i * 16 + (lane >> 2);
            uchar2 m0v = *(const uchar2*)&mrow[r * SEQ + c];
            uchar2 m1v = *(const uchar2*)&mrow[(r + 8) * SEQ + c];
            float2 o0, o1;
            o0.x = m0v.x ? __expf(acc[i][j][0] * 0.125f) : 0.f;
            o0.y = m0v.y ? __expf(acc[i][j][1] * 0.125f) : 0.f;
            o1.x = m1v.x ? __expf(acc[i][j][2] * 0.125f) : 0.f;
            o1.y = m1v.y ? __expf(acc[i][j][3] * 0.125f) : 0.f;
            __stcs(&out16[r * (SEQ/2) + kp],       packh2(o0.x, o0.y));
            __stcs(&out16[(r + 8) * (SEQ/2) + kp], packh2(o1.x, o1.y));
            rs[i][0] += o0.x + o0.y;
            rs[i][1] += o1.x + o1.y;
        }
    }
    #pragma unroll
    for (int i = 0; i < 2; i++)
        #pragma unroll
        for (int hh = 0; hh < 2; hh++) {
            float v = rs[i][hh];
            v += __shfl_xor_sync(0xffffffffu, v, 1);
            v += __shfl_xor_sync(0xffffffffu, v, 2);
            if ((lane & 3) == 0)
                sums[(warp >> 2) * 128 + wm + i * 16 + hh * 8 + (lane >> 2)] = v;
        }
    __syncthreads();
    if (tid < 128) {
        float tot = sums[tid] + sums[128 + tid];
        partial[((size_t)bh_i * SEQ + q0 + tid) * NKT + blockIdx.y] = tot;
    }
}

// ---------------------------------------------------------------------------
// Fused PV (f16 mma, full-K), cp.async 3-stage. grid (16 qtile, 32 bh).
// ---------------------------------------------------------------------------
__global__ __launch_bounds__(256, 4)
void pv_norm16(const unsigned* __restrict__ p16, const unsigned* __restrict__ gv16,
               const float* __restrict__ partial, float* __restrict__ attn,
               float* __restrict__ ctx) {
    extern __shared__ unsigned pvs[];
    unsigned* Ps = pvs;                      // [PV16STG][128][20]
    unsigned* Vs = pvs + PV16_PS;            // [PV16STG][16][68]
    float* inv_s = (float*)(pvs + PV16_PS + PV16_VS);

    const int tid = threadIdx.x, lane = tid & 31, warp = tid >> 5;
    const int wm = (warp & 3) * 32, wn = (warp >> 2) * 32, kq = lane & 3;
    const int bh_i = blockIdx.y, b = bh_i >> 4, h = bh_i & 15;
    const unsigned* P16 = p16 + (size_t)bh_i * SEQ * (SEQ / 2);
    float* Pout = attn + (size_t)bh_i * SEQ * SEQ;
    const unsigned* V16 = gv16 + (size_t)b * (SEQ / 2) * DMODEL + h * DHEAD;
    float* Cc = ctx + (size_t)b * SEQ * DMODEL + h * DHEAD;
    const int q0 = blockIdx.x * 128;
    const int ntiles = SEQ / 32;

    auto prefetch = [&](int t) {
        int s = t % PV16STG;
        int kp0 = t * 16;
        #pragma unroll
        for (int l = 0; l < 2; l++) {
            int idx = tid + l * 256, r = idx >> 2, k4 = (idx & 3) * 4;
            cpasync16(&Ps[s*2560 + r*20 + k4], &P16[(size_t)(q0+r)*(SEQ/2) + kp0 + k4]);
        }
        {
            int kp = tid >> 4, n4 = (tid & 15) * 4;
            cpasync16(&Vs[s*1088 + kp*68 + n4], &V16[(size_t)(kp0+kp)*DMODEL + n4]);
        }
        asm volatile("cp.async.commit_group;");
    };
    #pragma unroll
    for (int t = 0; t < PV16STG - 1; t++) prefetch(t);

    if (tid < 128) {
        const float4* pp = (const float4*)&partial[((size_t)bh_i * SEQ + q0 + tid) * NKT];
        float4 p0 = pp[0], p1 = pp[1], p2 = pp[2], p3 = pp[3];
        float s = ((p0.x + p0.y) + (p0.z + p0.w)) + ((p1.x + p1.y) + (p1.z + p1.w))
                + ((p2.x + p2.y) + (p2.z + p2.w)) + ((p3.x + p3.y) + (p3.z + p3.w));
        inv_s[tid] = 1.0f / s;
    }

    float acc[2][4][4] = {};
    for (int t = 0; t < ntiles; t++) {
        int s = t % PV16STG;
        asm volatile("cp.async.wait_group %0;" :: "n"(PV16STG - 2));
        __syncthreads();
        const unsigned* Pp = &Ps[s*2560];
        const unsigned* Vp = &Vs[s*1088];
        #pragma unroll
        for (int kk = 0; kk < 16; kk += 8) {
            unsigned af[2][4];
            #pragma unroll
            for (int i = 0; i < 2; i++) {
                int m0 = wm + i * 16 + (lane >> 2);
                af[i][0] = Pp[m0*20 + kk+kq];     af[i][1] = Pp[(m0+8)*20 + kk+kq];
                af[i][2] = Pp[m0*20 + kk+kq+4];   af[i][3] = Pp[(m0+8)*20 + kk+kq+4];
            }
            #pragma unroll
            for (int j = 0; j < 4; j++) {
                int nb = wn + j * 8 + (lane >> 2);
                unsigned bf[2] = {Vp[(kk+kq)*68 + nb], Vp[(kk+kq+4)*68 + nb]};
                mma16h(acc[0][j], af[0], bf);
                mma16h(acc[1][j], af[1], bf);
            }
        }
        {
            int kcol = t * 32;
            #pragma unroll
            for (int l = 0; l < 2; l++) {
                int idx = tid + l * 256, r = idx >> 2, k4 = (idx & 3) * 4;
                float sc = inv_s[r];
                float4 o0, o1;
                float2 f;
                f = unpackh2(Pp[r*20 + k4 + 0]); o0.x = f.x * sc; o0.y = f.y * sc;
                f = unpackh2(Pp[r*20 + k4 + 1]); o0.z = f.x * sc; o0.w = f.y * sc;
                f = unpackh2(Pp[r*20 + k4 + 2]); o1.x = f.x * sc; o1.y = f.y * sc;
                f = unpackh2(Pp[r*20 + k4 + 3]); o1.z = f.x * sc; o1.w = f.y * sc;
                size_t base = (size_t)(q0 + r) * SEQ + kcol + k4 * 2;
                __stcs((float4*)&Pout[base],     o0);
                __stcs((float4*)&Pout[base + 4], o1);
            }
        }
        __syncthreads();
        if (t + PV16STG - 1 < ntiles) prefetch(t + PV16STG - 1);
        else asm volatile("cp.async.commit_group;");
    }
    #pragma unroll
    for (int j = 0; j < 4; j++) {
        int c = wn + j * 8 + (lane & 3) * 2;
        #pragma unroll
        for (int i = 0; i < 2; i++) {
            int rl = wm + i * 16 + (lane >> 2);
            float sc0 = inv_s[rl], sc1 = inv_s[rl + 8];
            size_t r = q0 + rl;
            float2 o0 = {acc[i][j][0] * sc0, acc[i][j][1] * sc0};
            float2 o1 = {acc[i][j][2] * sc1, acc[i][j][3] * sc1};
            *(float2*)&Cc[r * DMODEL + c]       = o0;
            *(float2*)&Cc[(r + 8) * DMODEL + c] = o1;
        }
    }
}

// ---------------------------------------------------------------------------
// Residual + LayerNorm.
// ---------------------------------------------------------------------------
__global__ void ln_kernel(const float* __restrict__ resid,
                          const float* __restrict__ x,
                          const float* __restrict__ gamma,
                          const float* __restrict__ beta,
                          float* __restrict__ out) {
    const size_t row = blockIdx.x;
    const float4* xr = reinterpret_cast<const float4*>(x + row * DMODEL);
    const float4* rr = reinterpret_cast<const float4*>(resid + row * DMODEL);
    const int t = threadIdx.x;
    __shared__ float sred[8];

    float4 a = rr[t], bv = xr[t];
    float4 v = {a.x + bv.x, a.y + bv.y, a.z + bv.z, a.w + bv.w};
    float s = v.x + v.y + v.z + v.w;
    #pragma unroll
    for (int o = 16; o > 0; o >>= 1) s += __shfl_xor_sync(0xffffffffu, s, o);
    if ((t & 31) == 0) sred[t >> 5] = s;
    __syncthreads();
    float tot = 0.f;
    #pragma unroll
    for (int i = 0; i < 8; i++) tot += sred[i];
    const float mu = tot * (1.0f / DMODEL);
    __syncthreads();

    float dx = v.x - mu, dy = v.y - mu, dz = v.z - mu, dw = v.w - mu;
    float sq = dx*dx + dy*dy + dz*dz + dw*dw;
    #pragma unroll
    for (int o = 16; o > 0; o >>= 1) sq += __shfl_xor_sync(0xffffffffu, sq, o);
    if ((t & 31) == 0) sred[t >> 5] = sq;
    __syncthreads();
    float tot2 = 0.f;
    #pragma unroll
    for (int i = 0; i < 8; i++) tot2 += sred[i];
    const float inv = rsqrtf(tot2 * (1.0f / DMODEL) + 1e-5f);

    float4 g = reinterpret_cast<const float4*>(gamma)[t];
    float4 be = reinterpret_cast<const float4*>(beta)[t];
    float4 o;
    o.x = dx * inv * g.x + be.x;
    o.y = dy * inv * g.y + be.y;
    o.z = dz * inv * g.z + be.z;
    o.w = dw * inv * g.w + be.w;
    reinterpret_cast<float4*>(out + row * DMODEL)[t] = o;
}

// ---------------------------------------------------------------------------
extern "C" void kernel_launch(void* const* d_in, const int* in_sizes, int n_in,
                              void* d_out, int out_size) {
    const float* q     = (const float*)d_in[0];
    const float* k     = (const float*)d_in[1];
    const float* v     = (const float*)d_in[2];
    const int*   mask  = (const int*)  d_in[3];
    const float* wq    = (const float*)d_in[4];
    const float* bq    = (const float*)d_in[5];
    const float* wk    = (const float*)d_in[6];
    const float* bk    = (const float*)d_in[7];
    const float* wv    = (const float*)d_in[8];
    const float* bv    = (const float*)d_in[9];
    const float* wo    = (const float*)d_in[10];
    const float* bo    = (const float*)d_in[11];
    const float* gamma = (const float*)d_in[12];
    const float* beta  = (const float*)d_in[13];

    float* out  = (float*)d_out;
    float* attn = out + ATT_OFF;

    void* sp = nullptr;
    cudaGetSymbolAddress(&sp, g_scratch);
    float* go      = (float*)sp;
    float* ctx     = go + PS;
    float* partial = ctx + PS;
    unsigned* ipk  = (unsigned*)(partial + PARTIAL_SZ);   // q,k hi/lo (4*PKA)
    unsigned* wpk  = ipk + 4 * PKA;                        // wq,wk hi/lo (4*PKW)
    unsigned* opk16= wpk + 4 * PKW;                        // gq16, gk16 (2*PKA)
    unsigned* gv16 = opk16 + 2 * PKA;                      // fp16 V kpairs
    unsigned* p16  = gv16 + GV16_SZ;                       // fp16 unnorm P
    unsigned char* mask8 = (unsigned char*)(p16 + P16_SZ); // uint8 mask

    cudaFuncSetAttribute(scores_exp,  cudaFuncAttributeMaxDynamicSharedMemorySize, SC_SMEM);
    cudaFuncSetAttribute(pv_norm16,   cudaFuncAttributeMaxDynamicSharedMemorySize, PV16_SMEM);
    cudaFuncSetAttribute(gemm_o_tf32, cudaFuncAttributeMaxDynamicSharedMemorySize, OP_SMEM);
    cudaFuncSetAttribute(gemm_proj,   cudaFuncAttributeMaxDynamicSharedMemorySize, PROJ_SMEM);

    dim3 gPre((unsigned)((PKA / 2 + 255) / 256), 4);
    prepack_all<<<gPre, 256>>>(q, k, wq, wk, ipk, wpk);

    prepack_mask<<<(unsigned)(M8_W / 256), 256>>>(mask, mask8);

    dim3 gProj3(DMODEL / 128, MROWS / 128, 3);          // (8, 32, 3): q, k, v
    gemm_proj<<<gProj3, 256, PROJ_SMEM>>>(ipk, wpk, v, wv, bq, bk, bv, opk16, gv16);

    dim3 gScores(BATCH * NHEADS, NKT, SEQ / 128);       // (32, 16, 16)
    scores_exp<<<gScores, 256, SC_SMEM>>>(opk16, mask8, p16, partial);

    dim3 gPV(SEQ / 128, BATCH * NHEADS);                // (16, 32)
    pv_norm16<<<gPV, 256, PV16_SMEM>>>(p16, gv16, partial, attn, ctx);

    dim3 gProj(DMODEL / 128, MROWS / 128);              // (8, 32)
    gemm_o_tf32<<<gProj, 256, OP_SMEM>>>(ctx, wo, bo, go);

    ln_kernel<<<MROWS, 256>>>(q, go, gamma, beta, out);
}